// round 11
// baseline (speedup 1.0000x reference)
#include <cuda_runtime.h>
#include <cstdint>

#define Bn 256
#define Tn 128
#define Dn 300
#define Hn 512
#define G4 2048
#define OUTD 200

typedef unsigned long long u64;

// -------- static scratch --------
__device__ float g_X[2][Tn * Bn * G4];        // input projections [t][b][2048]
__device__ float g_H1[2][Tn * Bn * Hn];       // layer1 h row-major (final gather)
// pair-layout h images, tf32-pre-rounded:
// [layer][enc][t][mhalf][row*256 + k8grp*4 + tig] float2 = {h[k], h[k+4]}
__device__ float2 g_Hp[2][2][Tn][2][128 * 256];
__device__ int g_cnt4[4];                      // per-(e,m) group barriers
__device__ int g_gen4[4];

// -------- tf32 / mma helpers --------
__device__ __forceinline__ uint32_t cvt_tf32(float f) {
    uint32_t r;
    asm("cvt.rna.tf32.f32 %0, %1;" : "=r"(r) : "f"(f));
    return r;
}
__device__ __forceinline__ float tf32f(float f) {
    return __uint_as_float(cvt_tf32(f));
}
__device__ __forceinline__ void mma8(float* d, uint32_t a0, uint32_t a1,
                                     uint32_t a2, uint32_t a3,
                                     uint32_t b0, uint32_t b1) {
    asm volatile(
        "mma.sync.aligned.m16n8k8.row.col.f32.tf32.tf32.f32 "
        "{%0,%1,%2,%3}, {%4,%5,%6,%7}, {%8,%9}, {%0,%1,%2,%3};"
        : "+f"(d[0]), "+f"(d[1]), "+f"(d[2]), "+f"(d[3])
        : "r"(a0), "r"(a1), "r"(a2), "r"(a3), "r"(b0), "r"(b1));
}
__device__ __forceinline__ uint32_t smem_u32(const void* p) {
    uint32_t a;
    asm("{ .reg .u64 t; cvta.to.shared.u64 t, %1; cvt.u32.u64 %0, t; }"
        : "=r"(a) : "l"(p));
    return a;
}
__device__ __forceinline__ u64 gaddr(const void* p) {
    u64 g;
    asm("cvta.to.global.u64 %0, %1;" : "=l"(g) : "l"(p));
    return g;
}

// -------- fast activations --------
__device__ __forceinline__ float fast_ex2(float x) {
    float y; asm("ex2.approx.f32 %0, %1;" : "=f"(y) : "f"(x)); return y;
}
__device__ __forceinline__ float fast_rcp(float x) {
    float y; asm("rcp.approx.f32 %0, %1;" : "=f"(y) : "f"(x)); return y;
}
__device__ __forceinline__ float sigf(float x) {
    return fast_rcp(1.0f + fast_ex2(-1.4426950408889634f * x));
}
__device__ __forceinline__ float tanhfast(float x) {
    return 2.0f * fast_rcp(1.0f + fast_ex2(-2.8853900817779268f * x)) - 1.0f;
}

__device__ __forceinline__ float4 gload4(const float* p, int k0, int K) {
    if (k0 + 3 < K) return *(const float4*)p;
    float4 v = make_float4(0.f, 0.f, 0.f, 0.f);
    if (k0 < K)     v.x = p[0];
    if (k0 + 1 < K) v.y = p[1];
    if (k0 + 2 < K) v.z = p[2];
    return v;
}

// ============================================================================
// Input-projection GEMM via tf32 mma.sync (unchanged, proven).
// ============================================================================
#define XP_PITCH 10

__global__ __launch_bounds__(256) void xproj_mma(
    const float* __restrict__ AL, const float* __restrict__ AR,
    const float* __restrict__ WL, const float* __restrict__ WR,
    const float* __restrict__ bL, const float* __restrict__ bR,
    int K, int mode)
{
    __shared__ __align__(16) float2 Apair[128 * XP_PITCH];
    __shared__ __align__(16) float2 Wpair[128 * XP_PITCH];

    const int e = blockIdx.z;
    const float* A    = e ? AR : AL;
    const float* W    = e ? WR : WL;
    const float* bias = e ? bR : bL;
    float* Out = g_X[e];

    const int m0 = blockIdx.x * 128;
    const int n0 = blockIdx.y * 128;
    const int tid = threadIdx.x, lane = tid & 31, wid = tid >> 5;
    const int wm = wid & 1, wn = wid >> 1;
    const int gid = lane >> 2, tig = lane & 3;

    const int tt = m0 >> 8, mh = (m0 >> 7) & 1;

    float d[4][4][4];
#pragma unroll
    for (int a = 0; a < 4; a++)
#pragma unroll
        for (int b = 0; b < 4; b++)
#pragma unroll
            for (int c = 0; c < 4; c++) d[a][b][c] = 0.0f;

    const int arow = tid >> 1, ag = tid & 1;
    const int wg = tid >> 7, wtk = (tid >> 5) & 3, wcc = tid & 31;

    const int nk = (K + 15) >> 4;
    for (int kc16 = 0; kc16 < nk; kc16++) {
        const int kc = kc16 * 16;
        __syncthreads();
        if (mode == 0) {
            int b = (m0 & 255) + arow;
            const float* ap = A + ((size_t)b * Tn + tt) * K + kc + ag * 8;
            int kb = kc + ag * 8;
            float4 lo = (kb     < K) ? gload4(ap, kb, K)
                                     : make_float4(0.f, 0.f, 0.f, 0.f);
            float4 hi = (kb + 4 < K) ? gload4(ap + 4, kb + 4, K)
                                     : make_float4(0.f, 0.f, 0.f, 0.f);
            float2* dst = &Apair[arow * XP_PITCH + ag * 4];
            dst[0] = make_float2(tf32f(lo.x), tf32f(hi.x));
            dst[1] = make_float2(tf32f(lo.y), tf32f(hi.y));
            dst[2] = make_float2(tf32f(lo.z), tf32f(hi.z));
            dst[3] = make_float2(tf32f(lo.w), tf32f(hi.w));
        } else {
            const float4* src = (const float4*)
                &g_Hp[0][e][tt][mh][(size_t)arow * 256 + ((kc >> 3) + ag) * 4];
            float4 v0 = src[0], v1 = src[1];
            float4* dst = (float4*)&Apair[arow * XP_PITCH + ag * 4];
            dst[0] = v0;
            dst[1] = v1;
        }
        {
            int k1 = kc + wg * 8 + wtk, k2 = k1 + 4;
            const float* wp1 = W + (size_t)k1 * G4 + n0 + wcc * 4;
            const float* wp2 = W + (size_t)k2 * G4 + n0 + wcc * 4;
            float4 lo = (k1 < K) ? *(const float4*)wp1
                                 : make_float4(0.f, 0.f, 0.f, 0.f);
            float4 hi = (k2 < K) ? *(const float4*)wp2
                                 : make_float4(0.f, 0.f, 0.f, 0.f);
            int c0 = wcc * 4, pidx = wg * 4 + wtk;
            Wpair[(c0 + 0) * XP_PITCH + pidx] = make_float2(tf32f(lo.x), tf32f(hi.x));
            Wpair[(c0 + 1) * XP_PITCH + pidx] = make_float2(tf32f(lo.y), tf32f(hi.y));
            Wpair[(c0 + 2) * XP_PITCH + pidx] = make_float2(tf32f(lo.z), tf32f(hi.z));
            Wpair[(c0 + 3) * XP_PITCH + pidx] = make_float2(tf32f(lo.w), tf32f(hi.w));
        }
        __syncthreads();
#pragma unroll
        for (int g = 0; g < 2; g++) {
            uint2 bf[4];
#pragma unroll
            for (int j = 0; j < 4; j++) {
                int col = wn * 32 + j * 8 + gid;
                bf[j] = *(const uint2*)&Wpair[col * XP_PITCH + g * 4 + tig];
            }
#pragma unroll
            for (int ms = 0; ms < 4; ms++) {
                int R = wm * 64 + ms * 16;
                uint2 alo = *(const uint2*)&Apair[(R + gid) * XP_PITCH + g * 4 + tig];
                uint2 ahi = *(const uint2*)&Apair[(R + 8 + gid) * XP_PITCH + g * 4 + tig];
#pragma unroll
                for (int j = 0; j < 4; j++)
                    mma8(d[ms][j], alo.x, ahi.x, alo.y, ahi.y, bf[j].x, bf[j].y);
            }
        }
    }

#pragma unroll
    for (int ms = 0; ms < 4; ms++) {
        int r = m0 + wm * 64 + ms * 16 + gid;
#pragma unroll
        for (int j = 0; j < 4; j++) {
            int n = n0 + wn * 32 + j * 8 + tig * 2;
            float2 bv = *(const float2*)&bias[n];
            *(float2*)&Out[(size_t)r * G4 + n] =
                make_float2(d[ms][j][0] + bv.x, d[ms][j][1] + bv.y);
            *(float2*)&Out[(size_t)(r + 8) * G4 + n] =
                make_float2(d[ms][j][2] + bv.x, d[ms][j][3] + bv.y);
        }
    }
}

// ============================================================================
// Persistent tf32 mma.sync LSTM layer — 2 CTAs/SM variant.
// 256 CTAs = e(2) x m(2) x s(64); 256 threads; __launch_bounds__(256,2).
// CTA tile: M=128 x N=32 (8 units x 4 gates) x K=512 per step.
// 8 warps = kgroup(2) x wm(4); warp tile 32x32 (all N). W fragments resident
// (64KB); h streamed via cp.async 2-stage ring; dual zs partial sums.
// Two co-resident CTAs per SM hide each other's sync/barrier latency.
// ============================================================================
#define WB_BYTES  65536                        // 64 k8 x 4 nt x 32 lanes x f2
#define ST_BYTES  20480                        // 128 rows x 10 f4 (8 data + 2 pad)
#define ZS_PITCH  34
#define ZS_FLTS   (128 * ZS_PITCH)
#define SMEM_DYN  (WB_BYTES + 2 * ST_BYTES)    // 106496 -> 2 CTAs/SM
#define A2_PITCH  20

__global__ __launch_bounds__(256, 2) void lstm_persist_mma(
    const float* __restrict__ WhL, const float* __restrict__ WhR, int layer)
{
    extern __shared__ __align__(16) char sm[];
    float2* WB = (float2*)sm;
    float*  zs0 = (float*)(sm + WB_BYTES);     // aliases stage bufs (post-GEMM)
    float*  zs1 = zs0 + ZS_FLTS;               // 2x17408B <= 2x20480B region
    const uint32_t smb = smem_u32(sm);
    const uint32_t stg_base = smb + WB_BYTES;

    const int tid = threadIdx.x, lane = tid & 31, wid = tid >> 5;
    const int wk = wid >> 2;                   // k-group 0/1
    const int wm = wid & 3;                    // 4 m-tiles (wn folded out, N=32)
    const int gid = lane >> 2, tig = lane & 3;
    const int e = blockIdx.x >> 7;
    const int m = (blockIdx.x >> 6) & 1;
    const int s = blockIdx.x & 63;             // unit slice: 8 units
    const int grp = blockIdx.x >> 6;           // (e,m) barrier group (64 CTAs)
    const int m0 = m * 128, u0 = s * 8;

    const float* Wh = e ? WhR : WhL;
    const float* X  = g_X[e];
    float* Hrow = g_H1[e];

    // ---- precompute W fragments in mma B-register order (tf32) ----
#pragma unroll 4
    for (int i = 0; i < 32; i++) {
        int idx = tid + 256 * i;               // 0..8191
        int ln = idx & 31, nt = (idx >> 5) & 3, ks = idx >> 7;
        int n = nt * 8 + (ln >> 2);            // 0..31 = gate*8 + unit
        int k = ks * 8 + (ln & 3);
        int col = ((n >> 3) << 9) + u0 + (n & 7);
        uint32_t b0 = cvt_tf32(Wh[(size_t)k * G4 + col]);
        uint32_t b1 = cvt_tf32(Wh[(size_t)(k + 4) * G4 + col]);
        WB[idx] = make_float2(__uint_as_float(b0), __uint_as_float(b1));
    }

    float creg[4];
#pragma unroll
    for (int i = 0; i < 4; i++) creg[i] = 0.0f;
    const int eu = tid & 7, erg = tid >> 3;    // 8 units x 32 row-groups

    // cp.async role: 4 x 16B per chunk (256 thr x 4 f4 = 128 rows x 8 f4)
    const int crow = tid >> 1, cc2 = (tid & 1) * 4;

    // ---- X prefetch for t=0 ----
    float xg[4][4];
    {
        const float* Xt = X + (size_t)m0 * G4 + u0;
#pragma unroll
        for (int q = 0; q < 4; q++) {
            const float* Xb = Xt + (size_t)(erg + 32 * q) * G4;
            xg[0][q] = Xb[eu];
            xg[1][q] = Xb[512 + eu];
            xg[2][q] = Xb[1024 + eu];
            xg[3][q] = Xb[1536 + eu];
        }
    }

    __syncthreads();

    for (int t = 0; t < Tn; t++) {
        if (t > 0) {
            float d[2][4][4];
#pragma unroll
            for (int a = 0; a < 2; a++)
#pragma unroll
                for (int b = 0; b < 4; b++)
#pragma unroll
                    for (int c = 0; c < 4; c++) d[a][b][c] = 0.0f;

            const u64 hglob = gaddr(&g_Hp[layer][e][t - 1][m][0]);

#define ISSUE_CHUNK(kc_, st_) do {                                          \
    uint32_t dstb = stg_base + (st_) * ST_BYTES;                            \
    u64 srcb = hglob + ((u64)(kc_) * 8 + (u64)crow * 128 + cc2) * 16;       \
    uint32_t da = dstb + (crow * 10 + cc2) * 16;                            \
    asm volatile("cp.async.cg.shared.global [%0], [%1], 16;" :: "r"(da), "l"(srcb)); \
    asm volatile("cp.async.cg.shared.global [%0], [%1], 16;" :: "r"(da + 16), "l"(srcb + 16)); \
    asm volatile("cp.async.cg.shared.global [%0], [%1], 16;" :: "r"(da + 32), "l"(srcb + 32)); \
    asm volatile("cp.async.cg.shared.global [%0], [%1], 16;" :: "r"(da + 48), "l"(srcb + 48)); \
    asm volatile("cp.async.commit_group;");                                 \
} while (0)

            ISSUE_CHUNK(0, 0);
            ISSUE_CHUNK(1, 1);

            for (int kc = 0; kc < 16; kc++) {
                if (kc < 15)
                    asm volatile("cp.async.wait_group 1;" ::: "memory");
                else
                    asm volatile("cp.async.wait_group 0;" ::: "memory");
                __syncthreads();                  // chunk kc visible to all
                const float2* A2 =
                    (const float2*)(sm + WB_BYTES + (kc & 1) * ST_BYTES);
#pragma unroll
                for (int j8 = 0; j8 < 2; j8++) {
                    int k8l = wk * 2 + j8;
                    int k8g = kc * 4 + k8l;
                    uint2 bf[4];
                    const float2* wbp = WB + ((size_t)k8g * 4) * 32 + lane;
#pragma unroll
                    for (int j = 0; j < 4; j++) bf[j] = *(const uint2*)&wbp[j * 32];
#pragma unroll
                    for (int ms = 0; ms < 2; ms++) {
                        int R = wm * 32 + ms * 16;
                        uint2 alo = *(const uint2*)&A2[(R + gid) * A2_PITCH + k8l * 4 + tig];
                        uint2 ahi = *(const uint2*)&A2[(R + 8 + gid) * A2_PITCH + k8l * 4 + tig];
#pragma unroll
                        for (int j = 0; j < 4; j++)
                            mma8(d[ms][j], alo.x, ahi.x, alo.y, ahi.y,
                                 bf[j].x, bf[j].y);
                    }
                }
                if (kc + 2 < 16) {
                    __syncthreads();              // stage (kc&1) free to overwrite
                    ISSUE_CHUNK(kc + 2, kc & 1);
                }
            }
#undef ISSUE_CHUNK
            __syncthreads();
            // ---- d -> zs (each k-group to its own buffer) ----
            float* zsw = wk ? zs1 : zs0;
#pragma unroll
            for (int ms = 0; ms < 2; ms++) {
                int r0 = wm * 32 + ms * 16 + gid;
#pragma unroll
                for (int j = 0; j < 4; j++) {
                    int c = j * 8 + tig * 2;
                    *(float2*)&zsw[r0 * ZS_PITCH + c] =
                        make_float2(d[ms][j][0], d[ms][j][1]);
                    *(float2*)&zsw[(r0 + 8) * ZS_PITCH + c] =
                        make_float2(d[ms][j][2], d[ms][j][3]);
                }
            }
            __syncthreads();
        }

        // ---- epilogue: cell update + h store (X pre-loaded in xg) ----
        {
            float* hw = (float*)&g_Hp[layer][e][t][m][0];
            float* hr = Hrow + ((size_t)t * Bn + m0) * Hn + u0;
            int pofs = s * 8 + ((eu & 3) << 1) + (eu >> 2);
#pragma unroll
            for (int q = 0; q < 4; q++) {
                int row = erg + 32 * q;
                float zi = xg[0][q], zj = xg[1][q];
                float zf = xg[2][q], zo = xg[3][q];
                if (t > 0) {
                    zi += zs0[row * ZS_PITCH + eu]      + zs1[row * ZS_PITCH + eu];
                    zj += zs0[row * ZS_PITCH + 8 + eu]  + zs1[row * ZS_PITCH + 8 + eu];
                    zf += zs0[row * ZS_PITCH + 16 + eu] + zs1[row * ZS_PITCH + 16 + eu];
                    zo += zs0[row * ZS_PITCH + 24 + eu] + zs1[row * ZS_PITCH + 24 + eu];
                }
                float cn = creg[q] * sigf(zf + 1.0f) + sigf(zi) * tanhfast(zj);
                creg[q] = cn;
                float hv = tanhfast(cn) * sigf(zo);
                if (layer) hr[(size_t)row * Hn + eu] = hv;
                hw[row * 512 + pofs] = __uint_as_float(cvt_tf32(hv));
            }
        }

        if (t != Tn - 1) {
            // ---- prefetch X[t+1] (overlaps barrier + next GEMM) ----
            {
                const float* Xt = X + ((size_t)(t + 1) * Bn + m0) * G4 + u0;
#pragma unroll
                for (int q = 0; q < 4; q++) {
                    const float* Xb = Xt + (size_t)(erg + 32 * q) * G4;
                    xg[0][q] = Xb[eu];
                    xg[1][q] = Xb[512 + eu];
                    xg[2][q] = Xb[1024 + eu];
                    xg[3][q] = Xb[1536 + eu];
                }
            }
            // ---- per-(e,m) group barrier (64 CTAs) ----
            __threadfence();
            __syncthreads();
            if (tid == 0) {
                int g = *((volatile int*)&g_gen4[grp]);
                if (atomicAdd(&g_cnt4[grp], 1) == 63) {
                    g_cnt4[grp] = 0;
                    __threadfence();
                    atomicAdd(&g_gen4[grp], 1);
                } else {
                    while (*((volatile int*)&g_gen4[grp]) == g) { }
                }
            }
            __syncthreads();
        }
    }
}

// ============================================================================
// Gather last valid timestep + final projection [B,1024]@[1024,200]
// ============================================================================
__global__ __launch_bounds__(256) void final_kernel(
    const int* __restrict__ lenL, const int* __restrict__ lenR,
    const float* __restrict__ Wt, float* __restrict__ out)
{
    __shared__ float v[2 * Hn];
    int b = blockIdx.x, tid = threadIdx.x;
    int iL = lenL[b] - 1, iR = lenR[b] - 1;
    const float* hL = &g_H1[0][((size_t)iL * Bn + b) * Hn];
    const float* hR = &g_H1[1][((size_t)iR * Bn + b) * Hn];
    v[tid]       = hL[tid];
    v[256 + tid] = hL[256 + tid];
    v[512 + tid] = hR[tid];
    v[768 + tid] = hR[256 + tid];
    __syncthreads();
    if (tid < OUTD) {
        float acc = 0.0f;
#pragma unroll 8
        for (int k = 0; k < 2 * Hn; k++)
            acc += v[k] * Wt[k * OUTD + tid];
        out[b * OUTD + tid] = acc;
    }
}

// ============================================================================
extern "C" void kernel_launch(void* const* d_in, const int* in_sizes, int n_in,
                              void* d_out, int out_size)
{
    const float* left  = (const float*)d_in[0];
    const float* right = (const float*)d_in[1];
    const int*   lenL  = (const int*)d_in[2];
    const int*   lenR  = (const int*)d_in[3];
    const float* lW0 = (const float*)d_in[4];
    const float* lb0 = (const float*)d_in[5];
    const float* lW1 = (const float*)d_in[6];
    const float* lb1 = (const float*)d_in[7];
    const float* rW0 = (const float*)d_in[8];
    const float* rb0 = (const float*)d_in[9];
    const float* rW1 = (const float*)d_in[10];
    const float* rb1 = (const float*)d_in[11];
    const float* tW  = (const float*)d_in[12];
    float* out = (float*)d_out;

    static int smem_set = 0;
    if (!smem_set) {
        cudaFuncSetAttribute(lstm_persist_mma,
                             cudaFuncAttributeMaxDynamicSharedMemorySize, SMEM_DYN);
        smem_set = 1;
    }

    dim3 gx(256, 16, 2);

    // layer 0
    xproj_mma<<<gx, 256>>>(left, right, lW0, rW0, lb0, rb0, Dn, 0);
    lstm_persist_mma<<<256, 256, SMEM_DYN>>>(lW0 + (size_t)Dn * G4,
                                             rW0 + (size_t)Dn * G4, 0);
    // layer 1 (reads layer-0 pair image directly)
    xproj_mma<<<gx, 256>>>(nullptr, nullptr, lW1, rW1, lb1, rb1, Hn, 1);
    lstm_persist_mma<<<256, 256, SMEM_DYN>>>(lW1 + (size_t)Hn * G4,
                                             rW1 + (size_t)Hn * G4, 1);
    // gather + output projection
    final_kernel<<<256, 256>>>(lenL, lenR, tW, out);
}

// round 12
// speedup vs baseline: 1.2047x; 1.2047x over previous
#include <cuda_runtime.h>
#include <cstdint>

#define Bn 256
#define Tn 128
#define Dn 300
#define Hn 512
#define G4 2048
#define OUTD 200

typedef unsigned long long u64;

// -------- static scratch --------
__device__ float g_X[2][Tn * Bn * G4];        // input projections [t][b][2048]
__device__ float g_H1[2][Tn * Bn * Hn];       // layer1 h row-major (final gather)
// pair-layout h images, tf32-pre-rounded:
// [layer][enc][t][mhalf][row*256 + k8grp*4 + tig] float2 = {h[k], h[k+4]}
__device__ float2 g_Hp[2][2][Tn][2][128 * 256];
__device__ int g_cnt4[4];                      // end-of-kernel group barriers
__device__ int g_gen4[4];
__device__ int g_pc[4][16];                    // per-(e,m) pair counters (dataflow)

// -------- tf32 / mma helpers --------
__device__ __forceinline__ uint32_t cvt_tf32(float f) {
    uint32_t r;
    asm("cvt.rna.tf32.f32 %0, %1;" : "=r"(r) : "f"(f));
    return r;
}
__device__ __forceinline__ float tf32f(float f) {
    return __uint_as_float(cvt_tf32(f));
}
__device__ __forceinline__ void mma8(float* d, uint32_t a0, uint32_t a1,
                                     uint32_t a2, uint32_t a3,
                                     uint32_t b0, uint32_t b1) {
    asm volatile(
        "mma.sync.aligned.m16n8k8.row.col.f32.tf32.tf32.f32 "
        "{%0,%1,%2,%3}, {%4,%5,%6,%7}, {%8,%9}, {%0,%1,%2,%3};"
        : "+f"(d[0]), "+f"(d[1]), "+f"(d[2]), "+f"(d[3])
        : "r"(a0), "r"(a1), "r"(a2), "r"(a3), "r"(b0), "r"(b1));
}
__device__ __forceinline__ uint32_t smem_u32(const void* p) {
    uint32_t a;
    asm("{ .reg .u64 t; cvta.to.shared.u64 t, %1; cvt.u32.u64 %0, t; }"
        : "=r"(a) : "l"(p));
    return a;
}
__device__ __forceinline__ u64 gaddr(const void* p) {
    u64 g;
    asm("cvta.to.global.u64 %0, %1;" : "=l"(g) : "l"(p));
    return g;
}
// dataflow guard: producers arrived when counter >= target
__device__ __forceinline__ void wait_pc(const int* p, int target) {
    u64 a = gaddr(p);
    int v;
    do {
        asm volatile("ld.acquire.gpu.global.s32 %0, [%1];" : "=r"(v) : "l"(a));
    } while (v < target);
}

// -------- fast activations --------
__device__ __forceinline__ float fast_ex2(float x) {
    float y; asm("ex2.approx.f32 %0, %1;" : "=f"(y) : "f"(x)); return y;
}
__device__ __forceinline__ float fast_rcp(float x) {
    float y; asm("rcp.approx.f32 %0, %1;" : "=f"(y) : "f"(x)); return y;
}
__device__ __forceinline__ float sigf(float x) {
    return fast_rcp(1.0f + fast_ex2(-1.4426950408889634f * x));
}
__device__ __forceinline__ float tanhfast(float x) {
    return 2.0f * fast_rcp(1.0f + fast_ex2(-2.8853900817779268f * x)) - 1.0f;
}

__device__ __forceinline__ float4 gload4(const float* p, int k0, int K) {
    if (k0 + 3 < K) return *(const float4*)p;
    float4 v = make_float4(0.f, 0.f, 0.f, 0.f);
    if (k0 < K)     v.x = p[0];
    if (k0 + 1 < K) v.y = p[1];
    if (k0 + 2 < K) v.z = p[2];
    return v;
}

// ============================================================================
// Input-projection GEMM via tf32 mma.sync (unchanged, proven).
// ============================================================================
#define XP_PITCH 10

__global__ __launch_bounds__(256) void xproj_mma(
    const float* __restrict__ AL, const float* __restrict__ AR,
    const float* __restrict__ WL, const float* __restrict__ WR,
    const float* __restrict__ bL, const float* __restrict__ bR,
    int K, int mode)
{
    __shared__ __align__(16) float2 Apair[128 * XP_PITCH];
    __shared__ __align__(16) float2 Wpair[128 * XP_PITCH];

    const int e = blockIdx.z;
    const float* A    = e ? AR : AL;
    const float* W    = e ? WR : WL;
    const float* bias = e ? bR : bL;
    float* Out = g_X[e];

    const int m0 = blockIdx.x * 128;
    const int n0 = blockIdx.y * 128;
    const int tid = threadIdx.x, lane = tid & 31, wid = tid >> 5;
    const int wm = wid & 1, wn = wid >> 1;
    const int gid = lane >> 2, tig = lane & 3;

    const int tt = m0 >> 8, mh = (m0 >> 7) & 1;

    float d[4][4][4];
#pragma unroll
    for (int a = 0; a < 4; a++)
#pragma unroll
        for (int b = 0; b < 4; b++)
#pragma unroll
            for (int c = 0; c < 4; c++) d[a][b][c] = 0.0f;

    const int arow = tid >> 1, ag = tid & 1;
    const int wg = tid >> 7, wtk = (tid >> 5) & 3, wcc = tid & 31;

    const int nk = (K + 15) >> 4;
    for (int kc16 = 0; kc16 < nk; kc16++) {
        const int kc = kc16 * 16;
        __syncthreads();
        if (mode == 0) {
            int b = (m0 & 255) + arow;
            const float* ap = A + ((size_t)b * Tn + tt) * K + kc + ag * 8;
            int kb = kc + ag * 8;
            float4 lo = (kb     < K) ? gload4(ap, kb, K)
                                     : make_float4(0.f, 0.f, 0.f, 0.f);
            float4 hi = (kb + 4 < K) ? gload4(ap + 4, kb + 4, K)
                                     : make_float4(0.f, 0.f, 0.f, 0.f);
            float2* dst = &Apair[arow * XP_PITCH + ag * 4];
            dst[0] = make_float2(tf32f(lo.x), tf32f(hi.x));
            dst[1] = make_float2(tf32f(lo.y), tf32f(hi.y));
            dst[2] = make_float2(tf32f(lo.z), tf32f(hi.z));
            dst[3] = make_float2(tf32f(lo.w), tf32f(hi.w));
        } else {
            const float4* src = (const float4*)
                &g_Hp[0][e][tt][mh][(size_t)arow * 256 + ((kc >> 3) + ag) * 4];
            float4 v0 = src[0], v1 = src[1];
            float4* dst = (float4*)&Apair[arow * XP_PITCH + ag * 4];
            dst[0] = v0;
            dst[1] = v1;
        }
        {
            int k1 = kc + wg * 8 + wtk, k2 = k1 + 4;
            const float* wp1 = W + (size_t)k1 * G4 + n0 + wcc * 4;
            const float* wp2 = W + (size_t)k2 * G4 + n0 + wcc * 4;
            float4 lo = (k1 < K) ? *(const float4*)wp1
                                 : make_float4(0.f, 0.f, 0.f, 0.f);
            float4 hi = (k2 < K) ? *(const float4*)wp2
                                 : make_float4(0.f, 0.f, 0.f, 0.f);
            int c0 = wcc * 4, pidx = wg * 4 + wtk;
            Wpair[(c0 + 0) * XP_PITCH + pidx] = make_float2(tf32f(lo.x), tf32f(hi.x));
            Wpair[(c0 + 1) * XP_PITCH + pidx] = make_float2(tf32f(lo.y), tf32f(hi.y));
            Wpair[(c0 + 2) * XP_PITCH + pidx] = make_float2(tf32f(lo.z), tf32f(hi.z));
            Wpair[(c0 + 3) * XP_PITCH + pidx] = make_float2(tf32f(lo.w), tf32f(hi.w));
        }
        __syncthreads();
#pragma unroll
        for (int g = 0; g < 2; g++) {
            uint2 bf[4];
#pragma unroll
            for (int j = 0; j < 4; j++) {
                int col = wn * 32 + j * 8 + gid;
                bf[j] = *(const uint2*)&Wpair[col * XP_PITCH + g * 4 + tig];
            }
#pragma unroll
            for (int ms = 0; ms < 4; ms++) {
                int R = wm * 64 + ms * 16;
                uint2 alo = *(const uint2*)&Apair[(R + gid) * XP_PITCH + g * 4 + tig];
                uint2 ahi = *(const uint2*)&Apair[(R + 8 + gid) * XP_PITCH + g * 4 + tig];
#pragma unroll
                for (int j = 0; j < 4; j++)
                    mma8(d[ms][j], alo.x, ahi.x, alo.y, ahi.y, bf[j].x, bf[j].y);
            }
        }
    }

#pragma unroll
    for (int ms = 0; ms < 4; ms++) {
        int r = m0 + wm * 64 + ms * 16 + gid;
#pragma unroll
        for (int j = 0; j < 4; j++) {
            int n = n0 + wn * 32 + j * 8 + tig * 2;
            float2 bv = *(const float2*)&bias[n];
            *(float2*)&Out[(size_t)r * G4 + n] =
                make_float2(d[ms][j][0] + bv.x, d[ms][j][1] + bv.y);
            *(float2*)&Out[(size_t)(r + 8) * G4 + n] =
                make_float2(d[ms][j][2] + bv.x, d[ms][j][3] + bv.y);
        }
    }
}

// ============================================================================
// Persistent tf32 mma.sync LSTM layer — R10 base + dataflow pair-counters.
// 128 CTAs = e(2) x m(2) x s(32), 512 threads, K-split warp groups.
// CTA: M=128 x N=64 x K=512 per step. NO per-step barrier: consumer chunk kc
// (units 32kc..32kc+31) waits only on producers s=2kc,2kc+1 via release/
// acquire counters -> CTAs free-run, skew absorbed by chunk pipeline.
// ============================================================================
#define WB_BYTES  131072
#define ST_BYTES  20480                        // 128 rows x 10 f4
#define ZS_FLTS   (128 * 66)
#define SMEM_DYN  (WB_BYTES + 2 * ZS_FLTS * 4) // 198656 (stages alias zs region)
#define A2_PITCH  20

__global__ __launch_bounds__(512, 1) void lstm_persist_mma(
    const float* __restrict__ WhL, const float* __restrict__ WhR, int layer)
{
    extern __shared__ __align__(16) char sm[];
    float2* WB = (float2*)sm;
    float*  zs0 = (float*)(sm + WB_BYTES);     // aliases stage bufs (post-GEMM)
    float*  zs1 = zs0 + ZS_FLTS;
    const uint32_t smb = smem_u32(sm);
    const uint32_t stg_base = smb + WB_BYTES;

    const int tid = threadIdx.x, lane = tid & 31, wid = tid >> 5;
    const int wk = wid >> 3;                   // k-group 0/1
    const int wm = (wid >> 1) & 3, wn = wid & 1;
    const int gid = lane >> 2, tig = lane & 3;
    const int e = blockIdx.x >> 6;
    const int m = (blockIdx.x >> 5) & 1;
    const int s = blockIdx.x & 31;
    const int grp = blockIdx.x >> 5;
    const int m0 = m * 128, u0 = s * 16;

    const float* Wh = e ? WhR : WhL;
    const float* X  = g_X[e];
    float* Hrow = g_H1[e];

    // ---- precompute W fragments in mma B-register order (tf32) ----
#pragma unroll 4
    for (int i = 0; i < 32; i++) {
        int idx = tid + 512 * i;
        int ln = idx & 31, nt = (idx >> 5) & 7, ks = idx >> 8;
        int n = nt * 8 + (ln >> 2);
        int k = ks * 8 + (ln & 3);
        int col = ((n >> 4) << 9) + u0 + (n & 15);
        uint32_t b0 = cvt_tf32(Wh[(size_t)k * G4 + col]);
        uint32_t b1 = cvt_tf32(Wh[(size_t)(k + 4) * G4 + col]);
        WB[idx] = make_float2(__uint_as_float(b0), __uint_as_float(b1));
    }

    float creg[4];
#pragma unroll
    for (int i = 0; i < 4; i++) creg[i] = 0.0f;
    const int eu = tid & 15, erg = (tid >> 4) & 31;

    // cp.async role: 2 x 16B per chunk (512 thr x 2 f4 = 128 rows x 8 f4)
    const int crow = tid >> 2, cc2 = (tid & 3) * 2;

    // ---- X prefetch for t=0 ----
    float xg[4][4];
    {
        const float* Xt = X + (size_t)m0 * G4 + u0;
#pragma unroll
        for (int q = 0; q < 4; q++) {
            const float* Xb = Xt + (size_t)(erg + 32 * q) * G4;
            xg[0][q] = Xb[eu];
            xg[1][q] = Xb[512 + eu];
            xg[2][q] = Xb[1024 + eu];
            xg[3][q] = Xb[1536 + eu];
        }
    }

    __syncthreads();

    for (int t = 0; t < Tn; t++) {
        if (t > 0) {
            const int target = 2 * t;          // both producers wrote h[t-1]
            float d[2][4][4];
#pragma unroll
            for (int a = 0; a < 2; a++)
#pragma unroll
                for (int b = 0; b < 4; b++)
#pragma unroll
                    for (int c = 0; c < 4; c++) d[a][b][c] = 0.0f;

            const u64 hglob = gaddr(&g_Hp[layer][e][t - 1][m][0]);

#define ISSUE_CHUNK(kc_, st_) do {                                          \
    uint32_t dstb = stg_base + (st_) * ST_BYTES;                            \
    u64 srcb = hglob + ((u64)(kc_) * 8 + (u64)crow * 128 + cc2) * 16;       \
    uint32_t da = dstb + (crow * 10 + cc2) * 16;                            \
    asm volatile("cp.async.cg.shared.global [%0], [%1], 16;" :: "r"(da), "l"(srcb)); \
    asm volatile("cp.async.cg.shared.global [%0], [%1], 16;" :: "r"(da + 16), "l"(srcb + 16)); \
    asm volatile("cp.async.commit_group;");                                 \
} while (0)

            wait_pc(&g_pc[grp][0], target);
            ISSUE_CHUNK(0, 0);
            wait_pc(&g_pc[grp][1], target);
            ISSUE_CHUNK(1, 1);

            for (int kc = 0; kc < 16; kc++) {
                if (kc < 14)
                    asm volatile("cp.async.wait_group 1;" ::: "memory");
                else
                    asm volatile("cp.async.wait_group 0;" ::: "memory");
                __syncthreads();
                if (kc + 2 < 16) {
                    wait_pc(&g_pc[grp][kc + 2], target);
                    ISSUE_CHUNK(kc + 2, (kc + 2) % 3);
                }
                const float2* A2 =
                    (const float2*)(sm + WB_BYTES + (kc % 3) * ST_BYTES);
#pragma unroll
                for (int j8 = 0; j8 < 2; j8++) {
                    int k8l = wk * 2 + j8;
                    int k8g = kc * 4 + k8l;
                    uint2 bf[4];
                    const float2* wbp = WB + ((size_t)k8g * 8 + wn * 4) * 32 + lane;
#pragma unroll
                    for (int j = 0; j < 4; j++) bf[j] = *(const uint2*)&wbp[j * 32];
#pragma unroll
                    for (int ms = 0; ms < 2; ms++) {
                        int R = wm * 32 + ms * 16;
                        uint2 alo = *(const uint2*)&A2[(R + gid) * A2_PITCH + k8l * 4 + tig];
                        uint2 ahi = *(const uint2*)&A2[(R + 8 + gid) * A2_PITCH + k8l * 4 + tig];
#pragma unroll
                        for (int j = 0; j < 4; j++)
                            mma8(d[ms][j], alo.x, ahi.x, alo.y, ahi.y,
                                 bf[j].x, bf[j].y);
                    }
                }
            }
#undef ISSUE_CHUNK
            __syncthreads();
            // ---- d -> zs (each k-group to its own buffer) ----
            float* zsw = wk ? zs1 : zs0;
#pragma unroll
            for (int ms = 0; ms < 2; ms++) {
                int r0 = wm * 32 + ms * 16 + gid;
#pragma unroll
                for (int j = 0; j < 4; j++) {
                    int c = wn * 32 + j * 8 + tig * 2;
                    *(float2*)&zsw[r0 * 66 + c] =
                        make_float2(d[ms][j][0], d[ms][j][1]);
                    *(float2*)&zsw[(r0 + 8) * 66 + c] =
                        make_float2(d[ms][j][2], d[ms][j][3]);
                }
            }
            __syncthreads();
        }

        // ---- epilogue: cell update + h store (X pre-loaded in xg) ----
        {
            float* hw = (float*)&g_Hp[layer][e][t][m][0];
            float* hr = Hrow + ((size_t)t * Bn + m0) * Hn + u0;
            int pofs = s * 16 + ((eu >> 3) << 3) + ((eu & 3) << 1) + ((eu >> 2) & 1);
#pragma unroll
            for (int q = 0; q < 4; q++) {
                int row = erg + 32 * q;
                float zi = xg[0][q], zj = xg[1][q];
                float zf = xg[2][q], zo = xg[3][q];
                if (t > 0) {
                    zi += zs0[row * 66 + eu]      + zs1[row * 66 + eu];
                    zj += zs0[row * 66 + 16 + eu] + zs1[row * 66 + 16 + eu];
                    zf += zs0[row * 66 + 32 + eu] + zs1[row * 66 + 32 + eu];
                    zo += zs0[row * 66 + 48 + eu] + zs1[row * 66 + 48 + eu];
                }
                float cn = creg[q] * sigf(zf + 1.0f) + sigf(zi) * tanhfast(zj);
                creg[q] = cn;
                float hv = tanhfast(cn) * sigf(zo);
                if (layer) hr[(size_t)row * Hn + eu] = hv;
                hw[row * 512 + pofs] = __uint_as_float(cvt_tf32(hv));
            }
        }

        // ---- dataflow arrive: h[t] slice published (release) ----
        __threadfence();
        __syncthreads();
        if (tid == 0) {
            u64 a = gaddr(&g_pc[grp][s >> 1]);
            int one = 1;
            asm volatile("red.release.gpu.global.add.s32 [%0], %1;"
                         :: "l"(a), "r"(one) : "memory");
        }

        // ---- prefetch X[t+1] (overlaps producers catching up) ----
        if (t != Tn - 1) {
            const float* Xt = X + ((size_t)(t + 1) * Bn + m0) * G4 + u0;
#pragma unroll
            for (int q = 0; q < 4; q++) {
                const float* Xb = Xt + (size_t)(erg + 32 * q) * G4;
                xg[0][q] = Xb[eu];
                xg[1][q] = Xb[512 + eu];
                xg[2][q] = Xb[1024 + eu];
                xg[3][q] = Xb[1536 + eu];
            }
        }
    }

    // ---- end-of-kernel group barrier, then reset counters for next launch ----
    __threadfence();
    __syncthreads();
    if (tid == 0) {
        int g = *((volatile int*)&g_gen4[grp]);
        if (atomicAdd(&g_cnt4[grp], 1) == 31) {
            g_cnt4[grp] = 0;
            __threadfence();
            atomicAdd(&g_gen4[grp], 1);
        } else {
            while (*((volatile int*)&g_gen4[grp]) == g) { }
        }
    }
    __syncthreads();
    if (tid == 0 && s < 16)
        *((volatile int*)&g_pc[grp][s]) = 0;
}

// ============================================================================
// Gather last valid timestep + final projection [B,1024]@[1024,200]
// ============================================================================
__global__ __launch_bounds__(256) void final_kernel(
    const int* __restrict__ lenL, const int* __restrict__ lenR,
    const float* __restrict__ Wt, float* __restrict__ out)
{
    __shared__ float v[2 * Hn];
    int b = blockIdx.x, tid = threadIdx.x;
    int iL = lenL[b] - 1, iR = lenR[b] - 1;
    const float* hL = &g_H1[0][((size_t)iL * Bn + b) * Hn];
    const float* hR = &g_H1[1][((size_t)iR * Bn + b) * Hn];
    v[tid]       = hL[tid];
    v[256 + tid] = hL[256 + tid];
    v[512 + tid] = hR[tid];
    v[768 + tid] = hR[256 + tid];
    __syncthreads();
    if (tid < OUTD) {
        float acc = 0.0f;
#pragma unroll 8
        for (int k = 0; k < 2 * Hn; k++)
            acc += v[k] * Wt[k * OUTD + tid];
        out[b * OUTD + tid] = acc;
    }
}

// ============================================================================
extern "C" void kernel_launch(void* const* d_in, const int* in_sizes, int n_in,
                              void* d_out, int out_size)
{
    const float* left  = (const float*)d_in[0];
    const float* right = (const float*)d_in[1];
    const int*   lenL  = (const int*)d_in[2];
    const int*   lenR  = (const int*)d_in[3];
    const float* lW0 = (const float*)d_in[4];
    const float* lb0 = (const float*)d_in[5];
    const float* lW1 = (const float*)d_in[6];
    const float* lb1 = (const float*)d_in[7];
    const float* rW0 = (const float*)d_in[8];
    const float* rb0 = (const float*)d_in[9];
    const float* rW1 = (const float*)d_in[10];
    const float* rb1 = (const float*)d_in[11];
    const float* tW  = (const float*)d_in[12];
    float* out = (float*)d_out;

    static int smem_set = 0;
    if (!smem_set) {
        cudaFuncSetAttribute(lstm_persist_mma,
                             cudaFuncAttributeMaxDynamicSharedMemorySize, SMEM_DYN);
        smem_set = 1;
    }

    dim3 gx(256, 16, 2);

    // layer 0
    xproj_mma<<<gx, 256>>>(left, right, lW0, rW0, lb0, rb0, Dn, 0);
    lstm_persist_mma<<<128, 512, SMEM_DYN>>>(lW0 + (size_t)Dn * G4,
                                             rW0 + (size_t)Dn * G4, 0);
    // layer 1 (reads layer-0 pair image directly)
    xproj_mma<<<gx, 256>>>(nullptr, nullptr, lW1, rW1, lb1, rb1, Hn, 1);
    lstm_persist_mma<<<128, 512, SMEM_DYN>>>(lW1 + (size_t)Hn * G4,
                                             rW1 + (size_t)Hn * G4, 1);
    // gather + output projection
    final_kernel<<<256, 256>>>(lenL, lenR, tW, out);
}

// round 13
// speedup vs baseline: 1.8615x; 1.5452x over previous
#include <cuda_runtime.h>
#include <cuda_fp16.h>
#include <cstdint>

#define Bn 256
#define Tn 128
#define Dn 300
#define Hn 512
#define G4 2048
#define OUTD 200

typedef unsigned long long u64;

// -------- static scratch --------
__device__ float g_X[2][Tn * Bn * G4];        // input projections [t][b][2048]
__device__ float g_H0[2][Tn * Bn * Hn];       // layer0 h row-major (xproj input)
__device__ float g_H1[2][Tn * Bn * Hn];       // layer1 h row-major (final gather)
// fp16 h image in m16n8k16 A-fragment order:
// [layer][e][t][mh][row*512 + p(k)], p(k)=(k>>4)*16+((k&7)>>1)*4+((k>>3)&1)*2+(k&1)
__device__ __half g_Hph[2][2][Tn][2][128 * 512];
__device__ int g_cnt4[4];                      // per-(e,m) group barriers
__device__ int g_gen4[4];

// -------- mma helpers --------
__device__ __forceinline__ uint32_t cvt_tf32(float f) {
    uint32_t r;
    asm("cvt.rna.tf32.f32 %0, %1;" : "=r"(r) : "f"(f));
    return r;
}
__device__ __forceinline__ float tf32f(float f) {
    return __uint_as_float(cvt_tf32(f));
}
// tf32 k8 (xproj)
__device__ __forceinline__ void mma8(float* d, uint32_t a0, uint32_t a1,
                                     uint32_t a2, uint32_t a3,
                                     uint32_t b0, uint32_t b1) {
    asm volatile(
        "mma.sync.aligned.m16n8k8.row.col.f32.tf32.tf32.f32 "
        "{%0,%1,%2,%3}, {%4,%5,%6,%7}, {%8,%9}, {%0,%1,%2,%3};"
        : "+f"(d[0]), "+f"(d[1]), "+f"(d[2]), "+f"(d[3])
        : "r"(a0), "r"(a1), "r"(a2), "r"(a3), "r"(b0), "r"(b1));
}
// fp16 k16 (recurrence)
__device__ __forceinline__ void mma16(float* d, uint32_t a0, uint32_t a1,
                                      uint32_t a2, uint32_t a3,
                                      uint32_t b0, uint32_t b1) {
    asm volatile(
        "mma.sync.aligned.m16n8k16.row.col.f32.f16.f16.f32 "
        "{%0,%1,%2,%3}, {%4,%5,%6,%7}, {%8,%9}, {%0,%1,%2,%3};"
        : "+f"(d[0]), "+f"(d[1]), "+f"(d[2]), "+f"(d[3])
        : "r"(a0), "r"(a1), "r"(a2), "r"(a3), "r"(b0), "r"(b1));
}
__device__ __forceinline__ uint32_t smem_u32(const void* p) {
    uint32_t a;
    asm("{ .reg .u64 t; cvta.to.shared.u64 t, %1; cvt.u32.u64 %0, t; }"
        : "=r"(a) : "l"(p));
    return a;
}
__device__ __forceinline__ u64 gaddr(const void* p) {
    u64 g;
    asm("cvta.to.global.u64 %0, %1;" : "=l"(g) : "l"(p));
    return g;
}
__device__ __forceinline__ uint32_t h2bits(float lo, float hi) {
    __half2 h = __floats2half2_rn(lo, hi);
    return *reinterpret_cast<uint32_t*>(&h);
}

// -------- fast activations --------
__device__ __forceinline__ float fast_ex2(float x) {
    float y; asm("ex2.approx.f32 %0, %1;" : "=f"(y) : "f"(x)); return y;
}
__device__ __forceinline__ float fast_rcp(float x) {
    float y; asm("rcp.approx.f32 %0, %1;" : "=f"(y) : "f"(x)); return y;
}
__device__ __forceinline__ float sigf(float x) {
    return fast_rcp(1.0f + fast_ex2(-1.4426950408889634f * x));
}
__device__ __forceinline__ float tanhfast(float x) {
    return 2.0f * fast_rcp(1.0f + fast_ex2(-2.8853900817779268f * x)) - 1.0f;
}

__device__ __forceinline__ float4 gload4(const float* p, int k0, int K) {
    if (k0 + 3 < K) return *(const float4*)p;
    float4 v = make_float4(0.f, 0.f, 0.f, 0.f);
    if (k0 < K)     v.x = p[0];
    if (k0 + 1 < K) v.y = p[1];
    if (k0 + 2 < K) v.z = p[2];
    return v;
}

// ============================================================================
// Input-projection GEMM via tf32 mma.sync.
// mode 0: A = embed [b][t][K] (K=300). mode 1: A = g_H0[e] row-major (K=512).
// ============================================================================
#define XP_PITCH 10

__global__ __launch_bounds__(256) void xproj_mma(
    const float* __restrict__ AL, const float* __restrict__ AR,
    const float* __restrict__ WL, const float* __restrict__ WR,
    const float* __restrict__ bL, const float* __restrict__ bR,
    int K, int mode)
{
    __shared__ __align__(16) float2 Apair[128 * XP_PITCH];
    __shared__ __align__(16) float2 Wpair[128 * XP_PITCH];

    const int e = blockIdx.z;
    const float* A    = mode ? g_H0[e] : (e ? AR : AL);
    const float* W    = e ? WR : WL;
    const float* bias = e ? bR : bL;
    float* Out = g_X[e];

    const int m0 = blockIdx.x * 128;
    const int n0 = blockIdx.y * 128;
    const int tid = threadIdx.x, lane = tid & 31, wid = tid >> 5;
    const int wm = wid & 1, wn = wid >> 1;
    const int gid = lane >> 2, tig = lane & 3;

    float d[4][4][4];
#pragma unroll
    for (int a = 0; a < 4; a++)
#pragma unroll
        for (int b = 0; b < 4; b++)
#pragma unroll
            for (int c = 0; c < 4; c++) d[a][b][c] = 0.0f;

    const int arow = tid >> 1, ag = tid & 1;
    const int wg = tid >> 7, wtk = (tid >> 5) & 3, wcc = tid & 31;

    // row offset: mode0 = embed [b][t][K] permuted, mode1 = row-major [r][512]
    const size_t arow_off = mode
        ? (size_t)(m0 + arow) * K
        : ((size_t)((m0 & 255) + arow) * Tn + (m0 >> 8)) * K;

    const int nk = (K + 15) >> 4;
    for (int kc16 = 0; kc16 < nk; kc16++) {
        const int kc = kc16 * 16;
        __syncthreads();
        {
            const float* ap = A + arow_off + kc + ag * 8;
            int kb = kc + ag * 8;
            float4 lo = (kb     < K) ? gload4(ap, kb, K)
                                     : make_float4(0.f, 0.f, 0.f, 0.f);
            float4 hi = (kb + 4 < K) ? gload4(ap + 4, kb + 4, K)
                                     : make_float4(0.f, 0.f, 0.f, 0.f);
            float2* dst = &Apair[arow * XP_PITCH + ag * 4];
            dst[0] = make_float2(tf32f(lo.x), tf32f(hi.x));
            dst[1] = make_float2(tf32f(lo.y), tf32f(hi.y));
            dst[2] = make_float2(tf32f(lo.z), tf32f(hi.z));
            dst[3] = make_float2(tf32f(lo.w), tf32f(hi.w));
        }
        {
            int k1 = kc + wg * 8 + wtk, k2 = k1 + 4;
            const float* wp1 = W + (size_t)k1 * G4 + n0 + wcc * 4;
            const float* wp2 = W + (size_t)k2 * G4 + n0 + wcc * 4;
            float4 lo = (k1 < K) ? *(const float4*)wp1
                                 : make_float4(0.f, 0.f, 0.f, 0.f);
            float4 hi = (k2 < K) ? *(const float4*)wp2
                                 : make_float4(0.f, 0.f, 0.f, 0.f);
            int c0 = wcc * 4, pidx = wg * 4 + wtk;
            Wpair[(c0 + 0) * XP_PITCH + pidx] = make_float2(tf32f(lo.x), tf32f(hi.x));
            Wpair[(c0 + 1) * XP_PITCH + pidx] = make_float2(tf32f(lo.y), tf32f(hi.y));
            Wpair[(c0 + 2) * XP_PITCH + pidx] = make_float2(tf32f(lo.z), tf32f(hi.z));
            Wpair[(c0 + 3) * XP_PITCH + pidx] = make_float2(tf32f(lo.w), tf32f(hi.w));
        }
        __syncthreads();
#pragma unroll
        for (int g = 0; g < 2; g++) {
            uint2 bf[4];
#pragma unroll
            for (int j = 0; j < 4; j++) {
                int col = wn * 32 + j * 8 + gid;
                bf[j] = *(const uint2*)&Wpair[col * XP_PITCH + g * 4 + tig];
            }
#pragma unroll
            for (int ms = 0; ms < 4; ms++) {
                int R = wm * 64 + ms * 16;
                uint2 alo = *(const uint2*)&Apair[(R + gid) * XP_PITCH + g * 4 + tig];
                uint2 ahi = *(const uint2*)&Apair[(R + 8 + gid) * XP_PITCH + g * 4 + tig];
#pragma unroll
                for (int j = 0; j < 4; j++)
                    mma8(d[ms][j], alo.x, ahi.x, alo.y, ahi.y, bf[j].x, bf[j].y);
            }
        }
    }

#pragma unroll
    for (int ms = 0; ms < 4; ms++) {
        int r = m0 + wm * 64 + ms * 16 + gid;
#pragma unroll
        for (int j = 0; j < 4; j++) {
            int n = n0 + wn * 32 + j * 8 + tig * 2;
            float2 bv = *(const float2*)&bias[n];
            *(float2*)&Out[(size_t)r * G4 + n] =
                make_float2(d[ms][j][0] + bv.x, d[ms][j][1] + bv.y);
            *(float2*)&Out[(size_t)(r + 8) * G4 + n] =
                make_float2(d[ms][j][2] + bv.x, d[ms][j][3] + bv.y);
        }
    }
}

// ============================================================================
// Persistent fp16 mma.sync LSTM layer (m16n8k16) — R10 structure.
// 128 CTAs = e(2) x m(2) x s(32), 512 threads, K-split warp groups (2).
// CTA: M=128 x N=64 x K=512 per step; 8 chunks of K=64, 3-stage cp.async ring,
// 1 syncthreads per chunk. W fragments resident in smem (fp16, 64KB).
// h image fp16 in fragment order -> staging is a raw copy, A-frag = 1 LDS.64.
// ============================================================================
#define WBH_BYTES 65536                        // 32 kg x 8 nt x 32 lanes x uint2
#define STG_BYTES 16384                        // 128 rows x 128B (K=64 fp16)
#define ZS_FLTS   (128 * 66)
#define SMEM_DYN  (WBH_BYTES + 2 * ZS_FLTS * 4)  // 133120; stages alias zs

__global__ __launch_bounds__(512, 1) void lstm_persist_mma(
    const float* __restrict__ WhL, const float* __restrict__ WhR, int layer)
{
    extern __shared__ __align__(16) char sm[];
    uint2* WB = (uint2*)sm;                    // W fragments
    float* zs0 = (float*)(sm + WBH_BYTES);     // aliases stage bufs (post-GEMM)
    float* zs1 = zs0 + ZS_FLTS;
    const uint32_t smb = smem_u32(sm);
    const uint32_t stg_base = smb + WBH_BYTES;

    const int tid = threadIdx.x, lane = tid & 31, wid = tid >> 5;
    const int wk = wid >> 3;                   // k-group 0/1
    const int wm = (wid >> 1) & 3, wn = wid & 1;
    const int gid = lane >> 2, tig = lane & 3;
    const int e = blockIdx.x >> 6;
    const int m = (blockIdx.x >> 5) & 1;
    const int s = blockIdx.x & 31;
    const int grp = blockIdx.x >> 5;
    const int m0 = m * 128, u0 = s * 16;

    const float* Wh = e ? WhR : WhL;
    const float* X  = g_X[e];

    // ---- precompute W fragments (fp16, mma B-reg order) ----
#pragma unroll 4
    for (int i = 0; i < 16; i++) {
        int idx = tid + 512 * i;               // 0..8191
        int ln = idx & 31, nt = (idx >> 5) & 7, kg = idx >> 8;  // kg 0..31
        int n = nt * 8 + (ln >> 2);            // 0..63 = gate*16'ish col index
        int k0 = kg * 16 + (ln & 3) * 2;
        int col = ((n >> 4) << 9) + u0 + (n & 15);
        uint32_t b0 = h2bits(Wh[(size_t)k0 * G4 + col],
                             Wh[(size_t)(k0 + 1) * G4 + col]);
        uint32_t b1 = h2bits(Wh[(size_t)(k0 + 8) * G4 + col],
                             Wh[(size_t)(k0 + 9) * G4 + col]);
        WB[idx] = make_uint2(b0, b1);
    }

    float creg[4];
#pragma unroll
    for (int i = 0; i < 4; i++) creg[i] = 0.0f;
    const int eu = tid & 15, erg = (tid >> 4) & 31;

    // cp.async role: 32B per thread per chunk (512 thr = 128 rows x 4 blocks)
    const int crow = tid >> 2, cblk = tid & 3;

    // ---- X prefetch for t=0 ----
    float xg[4][4];
    {
        const float* Xt = X + (size_t)m0 * G4 + u0;
#pragma unroll
        for (int q = 0; q < 4; q++) {
            const float* Xb = Xt + (size_t)(erg + 32 * q) * G4;
            xg[0][q] = Xb[eu];
            xg[1][q] = Xb[512 + eu];
            xg[2][q] = Xb[1024 + eu];
            xg[3][q] = Xb[1536 + eu];
        }
    }

    __syncthreads();

    for (int t = 0; t < Tn; t++) {
        if (t > 0) {
            float d[2][4][4];
#pragma unroll
            for (int a = 0; a < 2; a++)
#pragma unroll
                for (int b = 0; b < 4; b++)
#pragma unroll
                    for (int c = 0; c < 4; c++) d[a][b][c] = 0.0f;

            const u64 hglob = gaddr(&g_Hph[layer][e][t - 1][m][0]);

            // chunk kc = K columns [kc*64, kc*64+64): 128 rows x 128B, swizzled
#define ISSUE_CHUNK(kc_, st_) do {                                          \
    uint32_t dstb = stg_base + (st_) * STG_BYTES;                           \
    u64 srcb = hglob + (u64)crow * 1024 + (u64)(kc_) * 128 + cblk * 32;     \
    uint32_t da = dstb + crow * 128 + ((cblk ^ (crow & 3)) << 5);           \
    asm volatile("cp.async.cg.shared.global [%0], [%1], 16;" :: "r"(da), "l"(srcb)); \
    asm volatile("cp.async.cg.shared.global [%0], [%1], 16;" :: "r"(da + 16), "l"(srcb + 16)); \
    asm volatile("cp.async.commit_group;");                                 \
} while (0)

            ISSUE_CHUNK(0, 0);
            ISSUE_CHUNK(1, 1);

            for (int kc = 0; kc < 8; kc++) {
                if (kc < 7)
                    asm volatile("cp.async.wait_group 1;" ::: "memory");
                else
                    asm volatile("cp.async.wait_group 0;" ::: "memory");
                __syncthreads();
                if (kc + 2 < 8) ISSUE_CHUNK(kc + 2, (kc + 2) % 3);
                const char* stg = sm + WBH_BYTES + (kc % 3) * STG_BYTES;
#pragma unroll
                for (int j8 = 0; j8 < 2; j8++) {
                    int gl = wk * 2 + j8;      // k16 group within chunk (0..3)
                    int kg = kc * 4 + gl;      // global k16 group (0..31)
                    uint2 bf[4];
                    const uint2* wbp = WB + ((size_t)kg * 8 + wn * 4) * 32 + lane;
#pragma unroll
                    for (int j = 0; j < 4; j++) bf[j] = wbp[j * 32];
#pragma unroll
                    for (int ms = 0; ms < 2; ms++) {
                        int rlo = wm * 32 + ms * 16 + gid;
                        int rhi = rlo + 8;
                        uint2 alo = *(const uint2*)(stg + rlo * 128 +
                                        ((gl ^ (rlo & 3)) << 5) + tig * 8);
                        uint2 ahi = *(const uint2*)(stg + rhi * 128 +
                                        ((gl ^ (rhi & 3)) << 5) + tig * 8);
#pragma unroll
                        for (int j = 0; j < 4; j++)
                            mma16(d[ms][j], alo.x, ahi.x, alo.y, ahi.y,
                                  bf[j].x, bf[j].y);
                    }
                }
            }
#undef ISSUE_CHUNK
            __syncthreads();
            // ---- d -> zs (each k-group to its own buffer) ----
            float* zsw = wk ? zs1 : zs0;
#pragma unroll
            for (int ms = 0; ms < 2; ms++) {
                int r0 = wm * 32 + ms * 16 + gid;
#pragma unroll
                for (int j = 0; j < 4; j++) {
                    int c = wn * 32 + j * 8 + tig * 2;
                    *(float2*)&zsw[r0 * 66 + c] =
                        make_float2(d[ms][j][0], d[ms][j][1]);
                    *(float2*)&zsw[(r0 + 8) * 66 + c] =
                        make_float2(d[ms][j][2], d[ms][j][3]);
                }
            }
            __syncthreads();
        }

        // ---- epilogue: cell update + h stores (X pre-loaded in xg) ----
        {
            __half* hw = &g_Hph[layer][e][t][m][0];
            float* hr = (layer ? g_H1[e] : g_H0[e]) +
                        ((size_t)t * Bn + m0) * Hn + u0;
            // fragment-order position of unit u0+eu within its k16 group s
            int p = s * 16 + ((eu & 7) >> 1) * 4 + ((eu >> 3) & 1) * 2 + (eu & 1);
#pragma unroll
            for (int q = 0; q < 4; q++) {
                int row = erg + 32 * q;
                float zi = xg[0][q], zj = xg[1][q];
                float zf = xg[2][q], zo = xg[3][q];
                if (t > 0) {
                    zi += zs0[row * 66 + eu]      + zs1[row * 66 + eu];
                    zj += zs0[row * 66 + 16 + eu] + zs1[row * 66 + 16 + eu];
                    zf += zs0[row * 66 + 32 + eu] + zs1[row * 66 + 32 + eu];
                    zo += zs0[row * 66 + 48 + eu] + zs1[row * 66 + 48 + eu];
                }
                float cn = creg[q] * sigf(zf + 1.0f) + sigf(zi) * tanhfast(zj);
                creg[q] = cn;
                float hv = tanhfast(cn) * sigf(zo);
                hr[(size_t)row * Hn + eu] = hv;
                hw[row * 512 + p] = __float2half_rn(hv);
            }
        }

        if (t != Tn - 1) {
            // ---- prefetch X[t+1] (overlaps barrier + next GEMM) ----
            {
                const float* Xt = X + ((size_t)(t + 1) * Bn + m0) * G4 + u0;
#pragma unroll
                for (int q = 0; q < 4; q++) {
                    const float* Xb = Xt + (size_t)(erg + 32 * q) * G4;
                    xg[0][q] = Xb[eu];
                    xg[1][q] = Xb[512 + eu];
                    xg[2][q] = Xb[1024 + eu];
                    xg[3][q] = Xb[1536 + eu];
                }
            }
            // ---- per-(e,m) group barrier (32 CTAs) ----
            __threadfence();
            __syncthreads();
            if (tid == 0) {
                int g = *((volatile int*)&g_gen4[grp]);
                if (atomicAdd(&g_cnt4[grp], 1) == 31) {
                    g_cnt4[grp] = 0;
                    __threadfence();
                    atomicAdd(&g_gen4[grp], 1);
                } else {
                    while (*((volatile int*)&g_gen4[grp]) == g) { }
                }
            }
            __syncthreads();
        }
    }
}

// ============================================================================
// Gather last valid timestep + final projection [B,1024]@[1024,200]
// ============================================================================
__global__ __launch_bounds__(256) void final_kernel(
    const int* __restrict__ lenL, const int* __restrict__ lenR,
    const float* __restrict__ Wt, float* __restrict__ out)
{
    __shared__ float v[2 * Hn];
    int b = blockIdx.x, tid = threadIdx.x;
    int iL = lenL[b] - 1, iR = lenR[b] - 1;
    const float* hL = &g_H1[0][((size_t)iL * Bn + b) * Hn];
    const float* hR = &g_H1[1][((size_t)iR * Bn + b) * Hn];
    v[tid]       = hL[tid];
    v[256 + tid] = hL[256 + tid];
    v[512 + tid] = hR[tid];
    v[768 + tid] = hR[256 + tid];
    __syncthreads();
    if (tid < OUTD) {
        float acc = 0.0f;
#pragma unroll 8
        for (int k = 0; k < 2 * Hn; k++)
            acc += v[k] * Wt[k * OUTD + tid];
        out[b * OUTD + tid] = acc;
    }
}

// ============================================================================
extern "C" void kernel_launch(void* const* d_in, const int* in_sizes, int n_in,
                              void* d_out, int out_size)
{
    const float* left  = (const float*)d_in[0];
    const float* right = (const float*)d_in[1];
    const int*   lenL  = (const int*)d_in[2];
    const int*   lenR  = (const int*)d_in[3];
    const float* lW0 = (const float*)d_in[4];
    const float* lb0 = (const float*)d_in[5];
    const float* lW1 = (const float*)d_in[6];
    const float* lb1 = (const float*)d_in[7];
    const float* rW0 = (const float*)d_in[8];
    const float* rb0 = (const float*)d_in[9];
    const float* rW1 = (const float*)d_in[10];
    const float* rb1 = (const float*)d_in[11];
    const float* tW  = (const float*)d_in[12];
    float* out = (float*)d_out;

    static int smem_set = 0;
    if (!smem_set) {
        cudaFuncSetAttribute(lstm_persist_mma,
                             cudaFuncAttributeMaxDynamicSharedMemorySize, SMEM_DYN);
        smem_set = 1;
    }

    dim3 gx(256, 16, 2);

    // layer 0
    xproj_mma<<<gx, 256>>>(left, right, lW0, rW0, lb0, rb0, Dn, 0);
    lstm_persist_mma<<<128, 512, SMEM_DYN>>>(lW0 + (size_t)Dn * G4,
                                             rW0 + (size_t)Dn * G4, 0);
    // layer 1 (xproj reads layer-0 row-major h)
    xproj_mma<<<gx, 256>>>(nullptr, nullptr, lW1, rW1, lb1, rb1, Hn, 1);
    lstm_persist_mma<<<128, 512, SMEM_DYN>>>(lW1 + (size_t)Hn * G4,
                                             rW1 + (size_t)Hn * G4, 1);
    // gather + output projection
    final_kernel<<<256, 256>>>(lenL, lenR, tW, out);
}

// round 14
// speedup vs baseline: 2.0129x; 1.0813x over previous
#include <cuda_runtime.h>
#include <cuda_fp16.h>
#include <cstdint>

#define Bn 256
#define Tn 128
#define Dn 300
#define Hn 512
#define G4 2048
#define OUTD 200

typedef unsigned long long u64;

// -------- static scratch --------
__device__ float g_X[2][Tn * Bn * G4];        // input projections [t][b][2048]
__device__ float g_H1[2][Tn * Bn * Hn];       // layer1 h row-major (final gather)
// fp16 h image in m16n8k16 A-fragment order:
// [layer][e][t][mh][row*512 + p(k)], p within 16-group: ((k&7)>>1)*4+((k>>3)&1)*2+(k&1)
__device__ __half g_Hph[2][2][Tn][2][128 * 512];
__device__ int g_cnt4[4];                      // per-(e,m) group barriers
__device__ int g_gen4[4];

// -------- mma helpers --------
__device__ __forceinline__ void mma16(float* d, uint32_t a0, uint32_t a1,
                                      uint32_t a2, uint32_t a3,
                                      uint32_t b0, uint32_t b1) {
    asm volatile(
        "mma.sync.aligned.m16n8k16.row.col.f32.f16.f16.f32 "
        "{%0,%1,%2,%3}, {%4,%5,%6,%7}, {%8,%9}, {%0,%1,%2,%3};"
        : "+f"(d[0]), "+f"(d[1]), "+f"(d[2]), "+f"(d[3])
        : "r"(a0), "r"(a1), "r"(a2), "r"(a3), "r"(b0), "r"(b1));
}
__device__ __forceinline__ uint32_t smem_u32(const void* p) {
    uint32_t a;
    asm("{ .reg .u64 t; cvta.to.shared.u64 t, %1; cvt.u32.u64 %0, t; }"
        : "=r"(a) : "l"(p));
    return a;
}
__device__ __forceinline__ u64 gaddr(const void* p) {
    u64 g;
    asm("cvta.to.global.u64 %0, %1;" : "=l"(g) : "l"(p));
    return g;
}
__device__ __forceinline__ uint32_t h2bits(float lo, float hi) {
    __half2 h = __floats2half2_rn(lo, hi);
    return *reinterpret_cast<uint32_t*>(&h);
}

// -------- fast activations --------
__device__ __forceinline__ float fast_ex2(float x) {
    float y; asm("ex2.approx.f32 %0, %1;" : "=f"(y) : "f"(x)); return y;
}
__device__ __forceinline__ float fast_rcp(float x) {
    float y; asm("rcp.approx.f32 %0, %1;" : "=f"(y) : "f"(x)); return y;
}
__device__ __forceinline__ float sigf(float x) {
    return fast_rcp(1.0f + fast_ex2(-1.4426950408889634f * x));
}
__device__ __forceinline__ float tanhfast(float x) {
    return 2.0f * fast_rcp(1.0f + fast_ex2(-2.8853900817779268f * x)) - 1.0f;
}

__device__ __forceinline__ float4 gload4(const float* p, int k0, int K) {
    if (k0 + 3 < K) return *(const float4*)p;
    float4 v = make_float4(0.f, 0.f, 0.f, 0.f);
    if (k0 < K)     v.x = p[0];
    if (k0 + 1 < K) v.y = p[1];
    if (k0 + 2 < K) v.z = p[2];
    return v;
}

// ============================================================================
// Input-projection GEMM via fp16 mma.sync m16n8k16.
// X[r,n] = bias[n] + sum_k A[r,k]*W[k,n], r = t*256+b.
// CTA 128x128, K chunks of 16. 8 warps: wm(2) x wn(4); warp tile 64x32.
// Fragments staged in smem in pair-interleave order ({k,k+1,k+8,k+9} / 8B).
// mode 0: A = embed [b][t][K] (K=300, guarded). mode 1: A = g_Hph[0] image.
// ============================================================================
#define XA_PITCH 48   // bytes per 16-half row (32 data + 16 pad)

__global__ __launch_bounds__(256) void xproj_mma(
    const float* __restrict__ AL, const float* __restrict__ AR,
    const float* __restrict__ WL, const float* __restrict__ WR,
    const float* __restrict__ bL, const float* __restrict__ bR,
    int K, int mode)
{
    __shared__ __align__(16) char Asm[128 * XA_PITCH];
    __shared__ __align__(16) char Wsm[128 * XA_PITCH];

    const int e = blockIdx.z;
    const float* A    = e ? AR : AL;
    const float* W    = e ? WR : WL;
    const float* bias = e ? bR : bL;
    float* Out = g_X[e];

    const int m0 = blockIdx.x * 128;
    const int n0 = blockIdx.y * 128;
    const int tid = threadIdx.x, lane = tid & 31, wid = tid >> 5;
    const int wm = wid & 1, wn = wid >> 1;
    const int gid = lane >> 2, tig = lane & 3;
    const int tt = m0 >> 8, mh = (m0 >> 7) & 1;

    float d[4][4][4];
#pragma unroll
    for (int a = 0; a < 4; a++)
#pragma unroll
        for (int b = 0; b < 4; b++)
#pragma unroll
            for (int c = 0; c < 4; c++) d[a][b][c] = 0.0f;

    const int arow = tid >> 1, ag = tid & 1;             // A loader
    const int wg = tid >> 7, wtk = (tid >> 5) & 3, wcc = tid & 31;  // W loader

    const size_t arow_off = (mode == 0)
        ? ((size_t)((m0 & 255) + arow) * Tn + tt) * K : 0;
    const __half* himg = (mode == 1) ? &g_Hph[0][e][tt][mh][0] : nullptr;

    const int nk = (K + 15) >> 4;
    for (int kc16 = 0; kc16 < nk; kc16++) {
        const int kc = kc16 * 16;
        __syncthreads();
        // ---- stage A (pair-interleave fp16) ----
        if (mode == 0) {
            const float* ap = A + arow_off + kc + ag * 8;
            int kb = kc + ag * 8;
            float4 lo = (kb     < K) ? gload4(ap, kb, K)
                                     : make_float4(0.f, 0.f, 0.f, 0.f);
            float4 hi = (kb + 4 < K) ? gload4(ap + 4, kb + 4, K)
                                     : make_float4(0.f, 0.f, 0.f, 0.f);
            char* dst = Asm + arow * XA_PITCH + ag * 4;
            *(uint32_t*)(dst + 0)  = h2bits(lo.x, lo.y);
            *(uint32_t*)(dst + 8)  = h2bits(lo.z, lo.w);
            *(uint32_t*)(dst + 16) = h2bits(hi.x, hi.y);
            *(uint32_t*)(dst + 24) = h2bits(hi.z, hi.w);
        } else {
            // image is already in pair order: raw 16B copy per (row, half)
            const char* src = (const char*)(himg + (size_t)arow * 512 + kc) + ag * 16;
            char* dst = Asm + arow * XA_PITCH + ag * 16;
            *(uint2*)dst = *(const uint2*)src;
            *(uint2*)(dst + 8) = *(const uint2*)(src + 8);
        }
        // ---- stage W: thread covers pair {k1,k1+1} for 4 cols ----
        {
            int k1 = kc + wg * 8 + wtk * 2;
            const float* wp1 = W + (size_t)k1 * G4 + n0 + wcc * 4;
            const float* wp2 = W + (size_t)(k1 + 1) * G4 + n0 + wcc * 4;
            float4 lo = (k1     < K) ? *(const float4*)wp1
                                     : make_float4(0.f, 0.f, 0.f, 0.f);
            float4 hi = (k1 + 1 < K) ? *(const float4*)wp2
                                     : make_float4(0.f, 0.f, 0.f, 0.f);
            int off = wtk * 8 + wg * 4;
            *(uint32_t*)(Wsm + (wcc * 4 + 0) * XA_PITCH + off) = h2bits(lo.x, hi.x);
            *(uint32_t*)(Wsm + (wcc * 4 + 1) * XA_PITCH + off) = h2bits(lo.y, hi.y);
            *(uint32_t*)(Wsm + (wcc * 4 + 2) * XA_PITCH + off) = h2bits(lo.z, hi.z);
            *(uint32_t*)(Wsm + (wcc * 4 + 3) * XA_PITCH + off) = h2bits(lo.w, hi.w);
        }
        __syncthreads();
        // ---- compute: one k16 group, 16 mma16 per warp ----
        {
            uint2 bf[4];
#pragma unroll
            for (int j = 0; j < 4; j++) {
                int col = wn * 32 + j * 8 + gid;
                bf[j] = *(const uint2*)(Wsm + col * XA_PITCH + tig * 8);
            }
#pragma unroll
            for (int ms = 0; ms < 4; ms++) {
                int R = wm * 64 + ms * 16;
                uint2 alo = *(const uint2*)(Asm + (R + gid) * XA_PITCH + tig * 8);
                uint2 ahi = *(const uint2*)(Asm + (R + 8 + gid) * XA_PITCH + tig * 8);
#pragma unroll
                for (int j = 0; j < 4; j++)
                    mma16(d[ms][j], alo.x, ahi.x, alo.y, ahi.y, bf[j].x, bf[j].y);
            }
        }
    }

#pragma unroll
    for (int ms = 0; ms < 4; ms++) {
        int r = m0 + wm * 64 + ms * 16 + gid;
#pragma unroll
        for (int j = 0; j < 4; j++) {
            int n = n0 + wn * 32 + j * 8 + tig * 2;
            float2 bv = *(const float2*)&bias[n];
            *(float2*)&Out[(size_t)r * G4 + n] =
                make_float2(d[ms][j][0] + bv.x, d[ms][j][1] + bv.y);
            *(float2*)&Out[(size_t)(r + 8) * G4 + n] =
                make_float2(d[ms][j][2] + bv.x, d[ms][j][3] + bv.y);
        }
    }
}

// ============================================================================
// Persistent fp16 mma.sync LSTM layer (m16n8k16).
// 128 CTAs = e(2) x m(2) x s(32), 512 threads, K-split warp groups (2).
// CTA: M=128 x N=64 x K=512 per step; 4 chunks of K=128, 3-stage cp.async
// ring, 1 syncthreads per chunk. W fragments resident (fp16, 64KB).
// ============================================================================
#define WBH_BYTES 65536                        // 32 kg x 8 nt x 32 lanes x uint2
#define STG_BYTES 32768                        // 128 rows x 256B (K=128 fp16)
#define ZS_FLTS   (128 * 66)
#define SMEM_DYN  (WBH_BYTES + 3 * STG_BYTES)  // 163840; zs aliases stages

__global__ __launch_bounds__(512, 1) void lstm_persist_mma(
    const float* __restrict__ WhL, const float* __restrict__ WhR, int layer)
{
    extern __shared__ __align__(16) char sm[];
    uint2* WB = (uint2*)sm;                    // W fragments
    float* zs0 = (float*)(sm + WBH_BYTES);     // aliases stage bufs (post-GEMM)
    float* zs1 = zs0 + ZS_FLTS;
    const uint32_t smb = smem_u32(sm);
    const uint32_t stg_base = smb + WBH_BYTES;

    const int tid = threadIdx.x, lane = tid & 31, wid = tid >> 5;
    const int wk = wid >> 3;                   // k-group 0/1
    const int wm = (wid >> 1) & 3, wn = wid & 1;
    const int gid = lane >> 2, tig = lane & 3;
    const int e = blockIdx.x >> 6;
    const int m = (blockIdx.x >> 5) & 1;
    const int s = blockIdx.x & 31;
    const int grp = blockIdx.x >> 5;
    const int m0 = m * 128, u0 = s * 16;

    const float* Wh = e ? WhR : WhL;
    const float* X  = g_X[e];

    // ---- precompute W fragments (fp16, mma B-reg order) ----
#pragma unroll 4
    for (int i = 0; i < 16; i++) {
        int idx = tid + 512 * i;               // 0..8191
        int ln = idx & 31, nt = (idx >> 5) & 7, kg = idx >> 8;  // kg 0..31
        int n = nt * 8 + (ln >> 2);
        int k0 = kg * 16 + (ln & 3) * 2;
        int col = ((n >> 4) << 9) + u0 + (n & 15);
        uint32_t b0 = h2bits(Wh[(size_t)k0 * G4 + col],
                             Wh[(size_t)(k0 + 1) * G4 + col]);
        uint32_t b1 = h2bits(Wh[(size_t)(k0 + 8) * G4 + col],
                             Wh[(size_t)(k0 + 9) * G4 + col]);
        WB[idx] = make_uint2(b0, b1);
    }

    float creg[4];
#pragma unroll
    for (int i = 0; i < 4; i++) creg[i] = 0.0f;
    const int eu = tid & 15, erg = (tid >> 4) & 31;

    // cp.async role: 64B per thread per chunk (512 thr = 128 rows x 8 blocks)
    const int crow = tid >> 2, cb = (tid & 3) * 2;   // blocks cb, cb+1

    // ---- X prefetch for t=0 ----
    float xg[4][4];
    {
        const float* Xt = X + (size_t)m0 * G4 + u0;
#pragma unroll
        for (int q = 0; q < 4; q++) {
            const float* Xb = Xt + (size_t)(erg + 32 * q) * G4;
            xg[0][q] = Xb[eu];
            xg[1][q] = Xb[512 + eu];
            xg[2][q] = Xb[1024 + eu];
            xg[3][q] = Xb[1536 + eu];
        }
    }

    __syncthreads();

    for (int t = 0; t < Tn; t++) {
        if (t > 0) {
            float d[2][4][4];
#pragma unroll
            for (int a = 0; a < 2; a++)
#pragma unroll
                for (int b = 0; b < 4; b++)
#pragma unroll
                    for (int c = 0; c < 4; c++) d[a][b][c] = 0.0f;

            const u64 hglob = gaddr(&g_Hph[layer][e][t - 1][m][0]);

            // chunk kc = K cols [kc*128, +128): 128 rows x 256B, 32B-block swizzle
#define ISSUE_CHUNK(kc_, st_) do {                                          \
    uint32_t dstb = stg_base + (st_) * STG_BYTES;                           \
    u64 srcb = hglob + (u64)crow * 1024 + (u64)(kc_) * 256;                 \
    uint32_t da0 = dstb + crow * 256 + (((cb)     ^ (crow & 7)) << 5);      \
    uint32_t da1 = dstb + crow * 256 + (((cb + 1) ^ (crow & 7)) << 5);      \
    asm volatile("cp.async.cg.shared.global [%0], [%1], 16;" :: "r"(da0), "l"(srcb + cb * 32)); \
    asm volatile("cp.async.cg.shared.global [%0], [%1], 16;" :: "r"(da0 + 16), "l"(srcb + cb * 32 + 16)); \
    asm volatile("cp.async.cg.shared.global [%0], [%1], 16;" :: "r"(da1), "l"(srcb + cb * 32 + 32)); \
    asm volatile("cp.async.cg.shared.global [%0], [%1], 16;" :: "r"(da1 + 16), "l"(srcb + cb * 32 + 48)); \
    asm volatile("cp.async.commit_group;");                                 \
} while (0)

            ISSUE_CHUNK(0, 0);
            ISSUE_CHUNK(1, 1);

            for (int kc = 0; kc < 4; kc++) {
                if (kc < 3)
                    asm volatile("cp.async.wait_group 1;" ::: "memory");
                else
                    asm volatile("cp.async.wait_group 0;" ::: "memory");
                __syncthreads();
                if (kc + 2 < 4) ISSUE_CHUNK(kc + 2, (kc + 2) % 3);
                const char* stg = sm + WBH_BYTES + (kc % 3) * STG_BYTES;
#pragma unroll
                for (int j8 = 0; j8 < 4; j8++) {
                    int gl = wk * 4 + j8;      // k16 group within chunk (0..7)
                    int kg = kc * 8 + gl;      // global k16 group (0..31)
                    uint2 bf[4];
                    const uint2* wbp = WB + ((size_t)kg * 8 + wn * 4) * 32 + lane;
#pragma unroll
                    for (int j = 0; j < 4; j++) bf[j] = wbp[j * 32];
#pragma unroll
                    for (int ms = 0; ms < 2; ms++) {
                        int rlo = wm * 32 + ms * 16 + gid;
                        int rhi = rlo + 8;
                        uint2 alo = *(const uint2*)(stg + rlo * 256 +
                                        ((gl ^ (rlo & 7)) << 5) + tig * 8);
                        uint2 ahi = *(const uint2*)(stg + rhi * 256 +
                                        ((gl ^ (rhi & 7)) << 5) + tig * 8);
#pragma unroll
                        for (int j = 0; j < 4; j++)
                            mma16(d[ms][j], alo.x, ahi.x, alo.y, ahi.y,
                                  bf[j].x, bf[j].y);
                    }
                }
            }
#undef ISSUE_CHUNK
            __syncthreads();
            // ---- d -> zs (each k-group to its own buffer) ----
            float* zsw = wk ? zs1 : zs0;
#pragma unroll
            for (int ms = 0; ms < 2; ms++) {
                int r0 = wm * 32 + ms * 16 + gid;
#pragma unroll
                for (int j = 0; j < 4; j++) {
                    int c = wn * 32 + j * 8 + tig * 2;
                    *(float2*)&zsw[r0 * 66 + c] =
                        make_float2(d[ms][j][0], d[ms][j][1]);
                    *(float2*)&zsw[(r0 + 8) * 66 + c] =
                        make_float2(d[ms][j][2], d[ms][j][3]);
                }
            }
            __syncthreads();
        }

        // ---- epilogue: cell update + h stores (X pre-loaded in xg) ----
        {
            __half* hw = &g_Hph[layer][e][t][m][0];
            float* hr = g_H1[e] + ((size_t)t * Bn + m0) * Hn + u0;
            int p = s * 16 + ((eu & 7) >> 1) * 4 + ((eu >> 3) & 1) * 2 + (eu & 1);
#pragma unroll
            for (int q = 0; q < 4; q++) {
                int row = erg + 32 * q;
                float zi = xg[0][q], zj = xg[1][q];
                float zf = xg[2][q], zo = xg[3][q];
                if (t > 0) {
                    zi += zs0[row * 66 + eu]      + zs1[row * 66 + eu];
                    zj += zs0[row * 66 + 16 + eu] + zs1[row * 66 + 16 + eu];
                    zf += zs0[row * 66 + 32 + eu] + zs1[row * 66 + 32 + eu];
                    zo += zs0[row * 66 + 48 + eu] + zs1[row * 66 + 48 + eu];
                }
                float cn = creg[q] * sigf(zf + 1.0f) + sigf(zi) * tanhfast(zj);
                creg[q] = cn;
                float hv = tanhfast(cn) * sigf(zo);
                if (layer) hr[(size_t)row * Hn + eu] = hv;   // final gather only
                hw[row * 512 + p] = __float2half_rn(hv);
            }
        }

        if (t != Tn - 1) {
            // ---- prefetch X[t+1] (overlaps barrier + next GEMM) ----
            {
                const float* Xt = X + ((size_t)(t + 1) * Bn + m0) * G4 + u0;
#pragma unroll
                for (int q = 0; q < 4; q++) {
                    const float* Xb = Xt + (size_t)(erg + 32 * q) * G4;
                    xg[0][q] = Xb[eu];
                    xg[1][q] = Xb[512 + eu];
                    xg[2][q] = Xb[1024 + eu];
                    xg[3][q] = Xb[1536 + eu];
                }
            }
            // ---- per-(e,m) group barrier (32 CTAs) ----
            __threadfence();
            __syncthreads();
            if (tid == 0) {
                int g = *((volatile int*)&g_gen4[grp]);
                if (atomicAdd(&g_cnt4[grp], 1) == 31) {
                    g_cnt4[grp] = 0;
                    __threadfence();
                    atomicAdd(&g_gen4[grp], 1);
                } else {
                    while (*((volatile int*)&g_gen4[grp]) == g) { }
                }
            }
            __syncthreads();
        }
    }
}

// ============================================================================
// Gather last valid timestep + final projection [B,1024]@[1024,200]
// ============================================================================
__global__ __launch_bounds__(256) void final_kernel(
    const int* __restrict__ lenL, const int* __restrict__ lenR,
    const float* __restrict__ Wt, float* __restrict__ out)
{
    __shared__ float v[2 * Hn];
    int b = blockIdx.x, tid = threadIdx.x;
    int iL = lenL[b] - 1, iR = lenR[b] - 1;
    const float* hL = &g_H1[0][((size_t)iL * Bn + b) * Hn];
    const float* hR = &g_H1[1][((size_t)iR * Bn + b) * Hn];
    v[tid]       = hL[tid];
    v[256 + tid] = hL[256 + tid];
    v[512 + tid] = hR[tid];
    v[768 + tid] = hR[256 + tid];
    __syncthreads();
    if (tid < OUTD) {
        float acc = 0.0f;
#pragma unroll 8
        for (int k = 0; k < 2 * Hn; k++)
            acc += v[k] * Wt[k * OUTD + tid];
        out[b * OUTD + tid] = acc;
    }
}

// ============================================================================
extern "C" void kernel_launch(void* const* d_in, const int* in_sizes, int n_in,
                              void* d_out, int out_size)
{
    const float* left  = (const float*)d_in[0];
    const float* right = (const float*)d_in[1];
    const int*   lenL  = (const int*)d_in[2];
    const int*   lenR  = (const int*)d_in[3];
    const float* lW0 = (const float*)d_in[4];
    const float* lb0 = (const float*)d_in[5];
    const float* lW1 = (const float*)d_in[6];
    const float* lb1 = (const float*)d_in[7];
    const float* rW0 = (const float*)d_in[8];
    const float* rb0 = (const float*)d_in[9];
    const float* rW1 = (const float*)d_in[10];
    const float* rb1 = (const float*)d_in[11];
    const float* tW  = (const float*)d_in[12];
    float* out = (float*)d_out;

    static int smem_set = 0;
    if (!smem_set) {
        cudaFuncSetAttribute(lstm_persist_mma,
                             cudaFuncAttributeMaxDynamicSharedMemorySize, SMEM_DYN);
        smem_set = 1;
    }

    dim3 gx(256, 16, 2);

    // layer 0
    xproj_mma<<<gx, 256>>>(left, right, lW0, rW0, lb0, rb0, Dn, 0);
    lstm_persist_mma<<<128, 512, SMEM_DYN>>>(lW0 + (size_t)Dn * G4,
                                             rW0 + (size_t)Dn * G4, 0);
    // layer 1 (xproj reads layer-0 fp16 pair image directly)
    xproj_mma<<<gx, 256>>>(nullptr, nullptr, lW1, rW1, lb1, rb1, Hn, 1);
    lstm_persist_mma<<<128, 512, SMEM_DYN>>>(lW1 + (size_t)Hn * G4,
                                             rW1 + (size_t)Hn * G4, 1);
    // gather + output projection
    final_kernel<<<256, 256>>>(lenL, lenR, tW, out);
}

// round 15
// speedup vs baseline: 2.4826x; 1.2334x over previous
#include <cuda_runtime.h>
#include <cuda_fp16.h>
#include <cstdint>

#define Bn 256
#define Tn 128
#define Dn 300
#define Hn 512
#define G4 2048
#define OUTD 200

typedef unsigned long long u64;

// -------- static scratch --------
__device__ float g_X[2][Tn * Bn * G4];        // layer-0 input projections
__device__ float g_H1[2][Tn * Bn * Hn];       // layer1 h row-major (final gather)
// fp16 h images in m16n8k16 A-fragment order
__device__ __half g_Hph[2][2][Tn][2][128 * 512];
// W1x fragment image: [e][s][kg*256 + nt*32 + lane] uint2 (64KB per (e,s))
__device__ uint2 g_W1f[2][32][8192];
__device__ int g_cnt4[4];                      // per-(e,m) group barriers
__device__ int g_gen4[4];

// -------- mma helpers --------
__device__ __forceinline__ void mma16(float* d, uint32_t a0, uint32_t a1,
                                      uint32_t a2, uint32_t a3,
                                      uint32_t b0, uint32_t b1) {
    asm volatile(
        "mma.sync.aligned.m16n8k16.row.col.f32.f16.f16.f32 "
        "{%0,%1,%2,%3}, {%4,%5,%6,%7}, {%8,%9}, {%0,%1,%2,%3};"
        : "+f"(d[0]), "+f"(d[1]), "+f"(d[2]), "+f"(d[3])
        : "r"(a0), "r"(a1), "r"(a2), "r"(a3), "r"(b0), "r"(b1));
}
__device__ __forceinline__ uint32_t smem_u32(const void* p) {
    uint32_t a;
    asm("{ .reg .u64 t; cvta.to.shared.u64 t, %1; cvt.u32.u64 %0, t; }"
        : "=r"(a) : "l"(p));
    return a;
}
__device__ __forceinline__ u64 gaddr(const void* p) {
    u64 g;
    asm("cvta.to.global.u64 %0, %1;" : "=l"(g) : "l"(p));
    return g;
}
__device__ __forceinline__ uint32_t h2bits(float lo, float hi) {
    __half2 h = __floats2half2_rn(lo, hi);
    return *reinterpret_cast<uint32_t*>(&h);
}

// -------- fast activations --------
__device__ __forceinline__ float fast_ex2(float x) {
    float y; asm("ex2.approx.f32 %0, %1;" : "=f"(y) : "f"(x)); return y;
}
__device__ __forceinline__ float fast_rcp(float x) {
    float y; asm("rcp.approx.f32 %0, %1;" : "=f"(y) : "f"(x)); return y;
}
__device__ __forceinline__ float sigf(float x) {
    return fast_rcp(1.0f + fast_ex2(-1.4426950408889634f * x));
}
__device__ __forceinline__ float tanhfast(float x) {
    return 2.0f * fast_rcp(1.0f + fast_ex2(-2.8853900817779268f * x)) - 1.0f;
}

__device__ __forceinline__ float4 gload4(const float* p, int k0, int K) {
    if (k0 + 3 < K) return *(const float4*)p;
    float4 v = make_float4(0.f, 0.f, 0.f, 0.f);
    if (k0 < K)     v.x = p[0];
    if (k0 + 1 < K) v.y = p[1];
    if (k0 + 2 < K) v.z = p[2];
    return v;
}

// ============================================================================
// W1x fragment prep: rows 0..511 of W1 -> g_W1f[e][s] in mma B-reg order.
// ============================================================================
__global__ __launch_bounds__(256) void wprep1(
    const float* __restrict__ WL1, const float* __restrict__ WR1)
{
    const int e = blockIdx.y, s = blockIdx.x, u0 = s * 16;
    const float* Wx = e ? WR1 : WL1;           // rows 0..511 = x-part
    uint2* dst = g_W1f[e][s];
    const int tid = threadIdx.x;
#pragma unroll 4
    for (int i = 0; i < 32; i++) {
        int idx = tid + 256 * i;
        int ln = idx & 31, nt = (idx >> 5) & 7, kg = idx >> 8;
        int n = nt * 8 + (ln >> 2);
        int k0 = kg * 16 + (ln & 3) * 2;
        int col = ((n >> 4) << 9) + u0 + (n & 15);
        uint32_t b0 = h2bits(Wx[(size_t)k0 * G4 + col],
                             Wx[(size_t)(k0 + 1) * G4 + col]);
        uint32_t b1 = h2bits(Wx[(size_t)(k0 + 8) * G4 + col],
                             Wx[(size_t)(k0 + 9) * G4 + col]);
        dst[idx] = make_uint2(b0, b1);
    }
}

// ============================================================================
// Layer-0 input projection via fp16 mma.sync (embed only, K=300).
// ============================================================================
#define XA_PITCH 48

__global__ __launch_bounds__(256) void xproj_mma(
    const float* __restrict__ AL, const float* __restrict__ AR,
    const float* __restrict__ WL, const float* __restrict__ WR,
    const float* __restrict__ bL, const float* __restrict__ bR,
    int K)
{
    __shared__ __align__(16) char Asm[128 * XA_PITCH];
    __shared__ __align__(16) char Wsm[128 * XA_PITCH];

    const int e = blockIdx.z;
    const float* A    = e ? AR : AL;
    const float* W    = e ? WR : WL;
    const float* bias = e ? bR : bL;
    float* Out = g_X[e];

    const int m0 = blockIdx.x * 128;
    const int n0 = blockIdx.y * 128;
    const int tid = threadIdx.x, lane = tid & 31, wid = tid >> 5;
    const int wm = wid & 1, wn = wid >> 1;
    const int gid = lane >> 2, tig = lane & 3;
    const int tt = m0 >> 8;

    float d[4][4][4];
#pragma unroll
    for (int a = 0; a < 4; a++)
#pragma unroll
        for (int b = 0; b < 4; b++)
#pragma unroll
            for (int c = 0; c < 4; c++) d[a][b][c] = 0.0f;

    const int arow = tid >> 1, ag = tid & 1;
    const int wg = tid >> 7, wtk = (tid >> 5) & 3, wcc = tid & 31;
    const size_t arow_off = ((size_t)((m0 & 255) + arow) * Tn + tt) * K;

    const int nk = (K + 15) >> 4;
    for (int kc16 = 0; kc16 < nk; kc16++) {
        const int kc = kc16 * 16;
        __syncthreads();
        {
            const float* ap = A + arow_off + kc + ag * 8;
            int kb = kc + ag * 8;
            float4 lo = (kb     < K) ? gload4(ap, kb, K)
                                     : make_float4(0.f, 0.f, 0.f, 0.f);
            float4 hi = (kb + 4 < K) ? gload4(ap + 4, kb + 4, K)
                                     : make_float4(0.f, 0.f, 0.f, 0.f);
            char* dst = Asm + arow * XA_PITCH + ag * 4;
            *(uint32_t*)(dst + 0)  = h2bits(lo.x, lo.y);
            *(uint32_t*)(dst + 8)  = h2bits(lo.z, lo.w);
            *(uint32_t*)(dst + 16) = h2bits(hi.x, hi.y);
            *(uint32_t*)(dst + 24) = h2bits(hi.z, hi.w);
        }
        {
            int k1 = kc + wg * 8 + wtk * 2;
            const float* wp1 = W + (size_t)k1 * G4 + n0 + wcc * 4;
            const float* wp2 = W + (size_t)(k1 + 1) * G4 + n0 + wcc * 4;
            float4 lo = (k1     < K) ? *(const float4*)wp1
                                     : make_float4(0.f, 0.f, 0.f, 0.f);
            float4 hi = (k1 + 1 < K) ? *(const float4*)wp2
                                     : make_float4(0.f, 0.f, 0.f, 0.f);
            int off = wtk * 8 + wg * 4;
            *(uint32_t*)(Wsm + (wcc * 4 + 0) * XA_PITCH + off) = h2bits(lo.x, hi.x);
            *(uint32_t*)(Wsm + (wcc * 4 + 1) * XA_PITCH + off) = h2bits(lo.y, hi.y);
            *(uint32_t*)(Wsm + (wcc * 4 + 2) * XA_PITCH + off) = h2bits(lo.z, hi.z);
            *(uint32_t*)(Wsm + (wcc * 4 + 3) * XA_PITCH + off) = h2bits(lo.w, hi.w);
        }
        __syncthreads();
        {
            uint2 bf[4];
#pragma unroll
            for (int j = 0; j < 4; j++) {
                int col = wn * 32 + j * 8 + gid;
                bf[j] = *(const uint2*)(Wsm + col * XA_PITCH + tig * 8);
            }
#pragma unroll
            for (int ms = 0; ms < 4; ms++) {
                int R = wm * 64 + ms * 16;
                uint2 alo = *(const uint2*)(Asm + (R + gid) * XA_PITCH + tig * 8);
                uint2 ahi = *(const uint2*)(Asm + (R + 8 + gid) * XA_PITCH + tig * 8);
#pragma unroll
                for (int j = 0; j < 4; j++)
                    mma16(d[ms][j], alo.x, ahi.x, alo.y, ahi.y, bf[j].x, bf[j].y);
            }
        }
    }

#pragma unroll
    for (int ms = 0; ms < 4; ms++) {
        int r = m0 + wm * 64 + ms * 16 + gid;
#pragma unroll
        for (int j = 0; j < 4; j++) {
            int n = n0 + wn * 32 + j * 8 + tig * 2;
            float2 bv = *(const float2*)&bias[n];
            *(float2*)&Out[(size_t)r * G4 + n] =
                make_float2(d[ms][j][0] + bv.x, d[ms][j][1] + bv.y);
            *(float2*)&Out[(size_t)(r + 8) * G4 + n] =
                make_float2(d[ms][j][2] + bv.x, d[ms][j][3] + bv.y);
        }
    }
}

// ============================================================================
// Fused two-layer persistent LSTM (fp16 m16n8k16, layer-1 pipelined 1 behind).
// 128 CTAs = e(2) x m(2) x s(32), 512 threads = wk(2) x wm(4) x wn(2).
// Fused step tau: L0 step tau (z0 = X0[tau] + h0[tau-1]@W0h) and
//                 L1 step tau-1 (z1 = h0[tau-1]@W1x + h1[tau-2]@W1h + b1).
// W0h + W1h frags resident (128KB); W1x frags streamed with h0 chunks.
// ============================================================================
#define WB0_OFF   0
#define WB1_OFF   65536
#define STG_OFF   131072
#define H_STG     32768                        // h chunk: 128 rows x 256B
#define B1_STG    49152                        // h chunk + 16KB W frag chunk
#define ZS_FLTS   (128 * 66)
#define SMEM_DYN  (STG_OFF + 3 * H_STG)        // 229376

__global__ __launch_bounds__(512, 1) void lstm_fused(
    const float* __restrict__ W0L, const float* __restrict__ W0R,
    const float* __restrict__ W1L, const float* __restrict__ W1R,
    const float* __restrict__ b1L, const float* __restrict__ b1R)
{
    extern __shared__ __align__(16) char sm[];
    uint2* WB0 = (uint2*)(sm + WB0_OFF);
    uint2* WB1 = (uint2*)(sm + WB1_OFF);
    float* zs0 = (float*)(sm + STG_OFF);       // aliases staging (post-GEMM)
    float* zs1 = zs0 + ZS_FLTS;
    const uint32_t smb = smem_u32(sm);
    const uint32_t stgb = smb + STG_OFF;

    const int tid = threadIdx.x, lane = tid & 31, wid = tid >> 5;
    const int wk = wid >> 3;
    const int wm = (wid >> 1) & 3, wn = wid & 1;
    const int gid = lane >> 2, tig = lane & 3;
    const int e = blockIdx.x >> 6;
    const int m = (blockIdx.x >> 5) & 1;
    const int s = blockIdx.x & 31;
    const int grp = blockIdx.x >> 5;
    const int m0 = m * 128, u0 = s * 16;

    const float* W0h = (e ? W0R : W0L) + (size_t)Dn * G4;   // rows Dn..Dn+511
    const float* W1h = (e ? W1R : W1L) + (size_t)Hn * G4;   // rows 512..1023
    const float* B1  = e ? b1R : b1L;
    const float* X   = g_X[e];

    // ---- resident W fragments (W0h, W1h) ----
#pragma unroll 2
    for (int i = 0; i < 16; i++) {
        int idx = tid + 512 * i;
        int ln = idx & 31, nt = (idx >> 5) & 7, kg = idx >> 8;
        int n = nt * 8 + (ln >> 2);
        int k0 = kg * 16 + (ln & 3) * 2;
        int col = ((n >> 4) << 9) + u0 + (n & 15);
        WB0[idx] = make_uint2(
            h2bits(W0h[(size_t)k0 * G4 + col], W0h[(size_t)(k0 + 1) * G4 + col]),
            h2bits(W0h[(size_t)(k0 + 8) * G4 + col], W0h[(size_t)(k0 + 9) * G4 + col]));
        WB1[idx] = make_uint2(
            h2bits(W1h[(size_t)k0 * G4 + col], W1h[(size_t)(k0 + 1) * G4 + col]),
            h2bits(W1h[(size_t)(k0 + 8) * G4 + col], W1h[(size_t)(k0 + 9) * G4 + col]));
    }

    float creg0[4], creg1[4], b1v[4];
#pragma unroll
    for (int i = 0; i < 4; i++) { creg0[i] = 0.0f; creg1[i] = 0.0f; }
    const int eu = tid & 15, erg = (tid >> 4) & 31;
#pragma unroll
    for (int g = 0; g < 4; g++) b1v[g] = B1[(g << 9) + u0 + eu];

    const int crow = tid >> 2, cb = (tid & 3) * 2;   // h-chunk cp.async role
    const int p_img = s * 16 + ((eu & 7) >> 1) * 4 + ((eu >> 3) & 1) * 2 + (eu & 1);

    // ---- X prefetch for tau=0 ----
    float xg[4][4];
    {
        const float* Xt = X + (size_t)m0 * G4 + u0;
#pragma unroll
        for (int q = 0; q < 4; q++) {
            const float* Xb = Xt + (size_t)(erg + 32 * q) * G4;
            xg[0][q] = Xb[eu];   xg[1][q] = Xb[512 + eu];
            xg[2][q] = Xb[1024 + eu]; xg[3][q] = Xb[1536 + eu];
        }
    }

    __syncthreads();

// h chunk issue (4x16B per thread) into stage base 'dstb_'
#define ISSUE_H(hg_, kc_, dstb_) do {                                       \
    u64 srcb = (hg_) + (u64)crow * 1024 + (u64)(kc_) * 256;                 \
    uint32_t da0 = (dstb_) + crow * 256 + (((cb)     ^ (crow & 7)) << 5);   \
    uint32_t da1 = (dstb_) + crow * 256 + (((cb + 1) ^ (crow & 7)) << 5);   \
    asm volatile("cp.async.cg.shared.global [%0], [%1], 16;" :: "r"(da0), "l"(srcb + cb * 32)); \
    asm volatile("cp.async.cg.shared.global [%0], [%1], 16;" :: "r"(da0 + 16), "l"(srcb + cb * 32 + 16)); \
    asm volatile("cp.async.cg.shared.global [%0], [%1], 16;" :: "r"(da1), "l"(srcb + cb * 32 + 32)); \
    asm volatile("cp.async.cg.shared.global [%0], [%1], 16;" :: "r"(da1 + 16), "l"(srcb + cb * 32 + 48)); \
} while (0)
// W1x frag chunk issue (2x16B per thread) at dstb_ (16KB region)
#define ISSUE_W(wg_, kc_, dstb_) do {                                       \
    u64 srcw = (wg_) + (u64)(kc_) * 16384 + (u64)tid * 32;                  \
    uint32_t dw = (dstb_) + tid * 32;                                       \
    asm volatile("cp.async.cg.shared.global [%0], [%1], 16;" :: "r"(dw), "l"(srcw)); \
    asm volatile("cp.async.cg.shared.global [%0], [%1], 16;" :: "r"(dw + 16), "l"(srcw + 16)); \
} while (0)
#define COMMIT() asm volatile("cp.async.commit_group;")
#define WAITG(n_) asm volatile("cp.async.wait_group %0;" :: "n"(n_) : "memory")

    for (int tau = 0; tau <= Tn; tau++) {
        // ================= Phase A: layer 0, step tau =================
        if (tau < Tn) {
            if (tau > 0) {
                float d[2][4][4];
#pragma unroll
                for (int a = 0; a < 2; a++)
#pragma unroll
                    for (int b = 0; b < 4; b++)
#pragma unroll
                        for (int c = 0; c < 4; c++) d[a][b][c] = 0.0f;
                const u64 hg = gaddr(&g_Hph[0][e][tau - 1][m][0]);
                ISSUE_H(hg, 0, stgb); COMMIT();
                ISSUE_H(hg, 1, stgb + H_STG); COMMIT();
                for (int kc = 0; kc < 4; kc++) {
                    if (kc < 3) WAITG(1); else WAITG(0);
                    __syncthreads();
                    if (kc + 2 < 4) {
                        ISSUE_H(hg, kc + 2, stgb + ((kc + 2) % 3) * H_STG);
                        COMMIT();
                    }
                    const char* stg = sm + STG_OFF + (kc % 3) * H_STG;
                    const uint2* wc = WB0 + kc * 2048;
#pragma unroll
                    for (int j8 = 0; j8 < 4; j8++) {
                        int gl = wk * 4 + j8;
                        uint2 bf[4];
                        const uint2* wbp = wc + (gl * 8 + wn * 4) * 32 + lane;
#pragma unroll
                        for (int j = 0; j < 4; j++) bf[j] = wbp[j * 32];
#pragma unroll
                        for (int ms = 0; ms < 2; ms++) {
                            int rlo = wm * 32 + ms * 16 + gid, rhi = rlo + 8;
                            uint2 alo = *(const uint2*)(stg + rlo * 256 +
                                            ((gl ^ (rlo & 7)) << 5) + tig * 8);
                            uint2 ahi = *(const uint2*)(stg + rhi * 256 +
                                            ((gl ^ (rhi & 7)) << 5) + tig * 8);
#pragma unroll
                            for (int j = 0; j < 4; j++)
                                mma16(d[ms][j], alo.x, ahi.x, alo.y, ahi.y,
                                      bf[j].x, bf[j].y);
                        }
                    }
                }
                __syncthreads();
                float* zsw = wk ? zs1 : zs0;
#pragma unroll
                for (int ms = 0; ms < 2; ms++) {
                    int r0 = wm * 32 + ms * 16 + gid;
#pragma unroll
                    for (int j = 0; j < 4; j++) {
                        int c = wn * 32 + j * 8 + tig * 2;
                        *(float2*)&zsw[r0 * 66 + c] =
                            make_float2(d[ms][j][0], d[ms][j][1]);
                        *(float2*)&zsw[(r0 + 8) * 66 + c] =
                            make_float2(d[ms][j][2], d[ms][j][3]);
                    }
                }
                __syncthreads();
            }
            // epilogue 0
            {
                __half* hw = &g_Hph[0][e][tau][m][0];
#pragma unroll
                for (int q = 0; q < 4; q++) {
                    int row = erg + 32 * q;
                    float zi = xg[0][q], zj = xg[1][q];
                    float zf = xg[2][q], zo = xg[3][q];
                    if (tau > 0) {
                        zi += zs0[row * 66 + eu]      + zs1[row * 66 + eu];
                        zj += zs0[row * 66 + 16 + eu] + zs1[row * 66 + 16 + eu];
                        zf += zs0[row * 66 + 32 + eu] + zs1[row * 66 + 32 + eu];
                        zo += zs0[row * 66 + 48 + eu] + zs1[row * 66 + 48 + eu];
                    }
                    float cn = creg0[q] * sigf(zf + 1.0f) + sigf(zi) * tanhfast(zj);
                    creg0[q] = cn;
                    hw[row * 512 + p_img] = __float2half_rn(tanhfast(cn) * sigf(zo));
                }
            }
            __syncthreads();   // zs reads done before B1 staging overwrites
        }

        // ================= Phase B: layer 1, step tau-1 =================
        if (tau >= 1) {
            float d[2][4][4];
#pragma unroll
            for (int a = 0; a < 2; a++)
#pragma unroll
                for (int b = 0; b < 4; b++)
#pragma unroll
                    for (int c = 0; c < 4; c++) d[a][b][c] = 0.0f;

            // --- B1: h0[tau-1] @ W1x (streamed W frags), 2-stage 48KB ---
            {
                const u64 hg = gaddr(&g_Hph[0][e][tau - 1][m][0]);
                const u64 wg = gaddr(&g_W1f[e][s][0]);
                ISSUE_H(hg, 0, stgb); ISSUE_W(wg, 0, stgb + H_STG); COMMIT();
                ISSUE_H(hg, 1, stgb + B1_STG); ISSUE_W(wg, 1, stgb + B1_STG + H_STG); COMMIT();
                for (int kc = 0; kc < 4; kc++) {
                    if (kc < 3) WAITG(1); else WAITG(0);
                    __syncthreads();
                    const char* stg = sm + STG_OFF + (kc & 1) * B1_STG;
                    const uint2* wc = (const uint2*)(stg + H_STG);
#pragma unroll
                    for (int j8 = 0; j8 < 4; j8++) {
                        int gl = wk * 4 + j8;
                        uint2 bf[4];
                        const uint2* wbp = wc + (gl * 8 + wn * 4) * 32 + lane;
#pragma unroll
                        for (int j = 0; j < 4; j++) bf[j] = wbp[j * 32];
#pragma unroll
                        for (int ms = 0; ms < 2; ms++) {
                            int rlo = wm * 32 + ms * 16 + gid, rhi = rlo + 8;
                            uint2 alo = *(const uint2*)(stg + rlo * 256 +
                                            ((gl ^ (rlo & 7)) << 5) + tig * 8);
                            uint2 ahi = *(const uint2*)(stg + rhi * 256 +
                                            ((gl ^ (rhi & 7)) << 5) + tig * 8);
#pragma unroll
                            for (int j = 0; j < 4; j++)
                                mma16(d[ms][j], alo.x, ahi.x, alo.y, ahi.y,
                                      bf[j].x, bf[j].y);
                        }
                    }
                    if (kc + 2 < 4) {
                        __syncthreads();
                        ISSUE_H(hg, kc + 2, stgb + (kc & 1) * B1_STG);
                        ISSUE_W(wg, kc + 2, stgb + (kc & 1) * B1_STG + H_STG);
                        COMMIT();
                    }
                }
            }
            __syncthreads();   // B1 stage reads done before 32KB-layout reuse

            // --- B2: h1[tau-2] @ W1h (resident), 3-stage 32KB ---
            if (tau >= 2) {
                const u64 hg = gaddr(&g_Hph[1][e][tau - 2][m][0]);
                ISSUE_H(hg, 0, stgb); COMMIT();
                ISSUE_H(hg, 1, stgb + H_STG); COMMIT();
                for (int kc = 0; kc < 4; kc++) {
                    if (kc < 3) WAITG(1); else WAITG(0);
                    __syncthreads();
                    if (kc + 2 < 4) {
                        ISSUE_H(hg, kc + 2, stgb + ((kc + 2) % 3) * H_STG);
                        COMMIT();
                    }
                    const char* stg = sm + STG_OFF + (kc % 3) * H_STG;
                    const uint2* wc = WB1 + kc * 2048;
#pragma unroll
                    for (int j8 = 0; j8 < 4; j8++) {
                        int gl = wk * 4 + j8;
                        uint2 bf[4];
                        const uint2* wbp = wc + (gl * 8 + wn * 4) * 32 + lane;
#pragma unroll
                        for (int j = 0; j < 4; j++) bf[j] = wbp[j * 32];
#pragma unroll
                        for (int ms = 0; ms < 2; ms++) {
                            int rlo = wm * 32 + ms * 16 + gid, rhi = rlo + 8;
                            uint2 alo = *(const uint2*)(stg + rlo * 256 +
                                            ((gl ^ (rlo & 7)) << 5) + tig * 8);
                            uint2 ahi = *(const uint2*)(stg + rhi * 256 +
                                            ((gl ^ (rhi & 7)) << 5) + tig * 8);
#pragma unroll
                            for (int j = 0; j < 4; j++)
                                mma16(d[ms][j], alo.x, ahi.x, alo.y, ahi.y,
                                      bf[j].x, bf[j].y);
                        }
                    }
                }
            }
            __syncthreads();
            float* zsw = wk ? zs1 : zs0;
#pragma unroll
            for (int ms = 0; ms < 2; ms++) {
                int r0 = wm * 32 + ms * 16 + gid;
#pragma unroll
                for (int j = 0; j < 4; j++) {
                    int c = wn * 32 + j * 8 + tig * 2;
                    *(float2*)&zsw[r0 * 66 + c] =
                        make_float2(d[ms][j][0], d[ms][j][1]);
                    *(float2*)&zsw[(r0 + 8) * 66 + c] =
                        make_float2(d[ms][j][2], d[ms][j][3]);
                }
            }
            __syncthreads();
            // epilogue 1 (layer-1 step tau-1)
            {
                __half* hw = &g_Hph[1][e][tau - 1][m][0];
                float* hr = g_H1[e] + ((size_t)(tau - 1) * Bn + m0) * Hn + u0;
#pragma unroll
                for (int q = 0; q < 4; q++) {
                    int row = erg + 32 * q;
                    float zi = b1v[0] + zs0[row * 66 + eu]      + zs1[row * 66 + eu];
                    float zj = b1v[1] + zs0[row * 66 + 16 + eu] + zs1[row * 66 + 16 + eu];
                    float zf = b1v[2] + zs0[row * 66 + 32 + eu] + zs1[row * 66 + 32 + eu];
                    float zo = b1v[3] + zs0[row * 66 + 48 + eu] + zs1[row * 66 + 48 + eu];
                    float cn = creg1[q] * sigf(zf + 1.0f) + sigf(zi) * tanhfast(zj);
                    creg1[q] = cn;
                    float hv = tanhfast(cn) * sigf(zo);
                    hr[(size_t)row * Hn + eu] = hv;
                    hw[row * 512 + p_img] = __float2half_rn(hv);
                }
            }
        }

        if (tau < Tn) {
            // ---- prefetch X[tau+1] (overlaps barrier) ----
            if (tau < Tn - 1) {
                const float* Xt = X + ((size_t)(tau + 1) * Bn + m0) * G4 + u0;
#pragma unroll
                for (int q = 0; q < 4; q++) {
                    const float* Xb = Xt + (size_t)(erg + 32 * q) * G4;
                    xg[0][q] = Xb[eu];   xg[1][q] = Xb[512 + eu];
                    xg[2][q] = Xb[1024 + eu]; xg[3][q] = Xb[1536 + eu];
                }
            }
            // ---- per-(e,m) group barrier (32 CTAs) ----
            __threadfence();
            __syncthreads();
            if (tid == 0) {
                int g = *((volatile int*)&g_gen4[grp]);
                if (atomicAdd(&g_cnt4[grp], 1) == 31) {
                    g_cnt4[grp] = 0;
                    __threadfence();
                    atomicAdd(&g_gen4[grp], 1);
                } else {
                    while (*((volatile int*)&g_gen4[grp]) == g) { }
                }
            }
            __syncthreads();
        }
    }
#undef ISSUE_H
#undef ISSUE_W
#undef COMMIT
#undef WAITG
}

// ============================================================================
// Gather last valid timestep + final projection [B,1024]@[1024,200]
// ============================================================================
__global__ __launch_bounds__(256) void final_kernel(
    const int* __restrict__ lenL, const int* __restrict__ lenR,
    const float* __restrict__ Wt, float* __restrict__ out)
{
    __shared__ float v[2 * Hn];
    int b = blockIdx.x, tid = threadIdx.x;
    int iL = lenL[b] - 1, iR = lenR[b] - 1;
    const float* hL = &g_H1[0][((size_t)iL * Bn + b) * Hn];
    const float* hR = &g_H1[1][((size_t)iR * Bn + b) * Hn];
    v[tid]       = hL[tid];
    v[256 + tid] = hL[256 + tid];
    v[512 + tid] = hR[tid];
    v[768 + tid] = hR[256 + tid];
    __syncthreads();
    if (tid < OUTD) {
        float acc = 0.0f;
#pragma unroll 8
        for (int k = 0; k < 2 * Hn; k++)
            acc += v[k] * Wt[k * OUTD + tid];
        out[b * OUTD + tid] = acc;
    }
}

// ============================================================================
extern "C" void kernel_launch(void* const* d_in, const int* in_sizes, int n_in,
                              void* d_out, int out_size)
{
    const float* left  = (const float*)d_in[0];
    const float* right = (const float*)d_in[1];
    const int*   lenL  = (const int*)d_in[2];
    const int*   lenR  = (const int*)d_in[3];
    const float* lW0 = (const float*)d_in[4];
    const float* lb0 = (const float*)d_in[5];
    const float* lW1 = (const float*)d_in[6];
    const float* lb1 = (const float*)d_in[7];
    const float* rW0 = (const float*)d_in[8];
    const float* rb0 = (const float*)d_in[9];
    const float* rW1 = (const float*)d_in[10];
    const float* rb1 = (const float*)d_in[11];
    const float* tW  = (const float*)d_in[12];
    float* out = (float*)d_out;

    static int smem_set = 0;
    if (!smem_set) {
        cudaFuncSetAttribute(lstm_fused,
                             cudaFuncAttributeMaxDynamicSharedMemorySize, SMEM_DYN);
        smem_set = 1;
    }

    dim3 gx(256, 16, 2);
    dim3 gw(32, 2);

    wprep1<<<gw, 256>>>(lW1, rW1);                         // W1x frag image
    xproj_mma<<<gx, 256>>>(left, right, lW0, rW0, lb0, rb0, Dn);
    lstm_fused<<<128, 512, SMEM_DYN>>>(lW0, rW0, lW1, rW1, lb1, rb1);
    final_kernel<<<256, 256>>>(lenL, lenR, tW, out);
}

// round 16
// speedup vs baseline: 2.7084x; 1.0909x over previous
#include <cuda_runtime.h>
#include <cuda_fp16.h>
#include <cstdint>

#define Bn 256
#define Tn 128
#define Dn 300
#define Hn 512
#define G4 2048
#define OUTD 200

typedef unsigned long long u64;

// -------- static scratch --------
__device__ float g_X[2][Tn * Bn * G4];        // layer-0 input projections
__device__ float g_H1[2][Tn * Bn * Hn];       // layer1 h row-major (final gather)
__device__ __half g_Hph[2][2][Tn][2][128 * 512];  // fp16 h images, frag order
__device__ uint2 g_W1f[2][32][8192];          // W1x fragment image
__device__ int g_cnt4[4];
__device__ int g_gen4[4];

// -------- mma helpers --------
__device__ __forceinline__ void mma16(float* d, uint32_t a0, uint32_t a1,
                                      uint32_t a2, uint32_t a3,
                                      uint32_t b0, uint32_t b1) {
    asm volatile(
        "mma.sync.aligned.m16n8k16.row.col.f32.f16.f16.f32 "
        "{%0,%1,%2,%3}, {%4,%5,%6,%7}, {%8,%9}, {%0,%1,%2,%3};"
        : "+f"(d[0]), "+f"(d[1]), "+f"(d[2]), "+f"(d[3])
        : "r"(a0), "r"(a1), "r"(a2), "r"(a3), "r"(b0), "r"(b1));
}
__device__ __forceinline__ uint32_t smem_u32(const void* p) {
    uint32_t a;
    asm("{ .reg .u64 t; cvta.to.shared.u64 t, %1; cvt.u32.u64 %0, t; }"
        : "=r"(a) : "l"(p));
    return a;
}
__device__ __forceinline__ u64 gaddr(const void* p) {
    u64 g;
    asm("cvta.to.global.u64 %0, %1;" : "=l"(g) : "l"(p));
    return g;
}
__device__ __forceinline__ uint32_t h2bits(float lo, float hi) {
    __half2 h = __floats2half2_rn(lo, hi);
    return *reinterpret_cast<uint32_t*>(&h);
}

// -------- fast activations --------
__device__ __forceinline__ float fast_ex2(float x) {
    float y; asm("ex2.approx.f32 %0, %1;" : "=f"(y) : "f"(x)); return y;
}
__device__ __forceinline__ float fast_rcp(float x) {
    float y; asm("rcp.approx.f32 %0, %1;" : "=f"(y) : "f"(x)); return y;
}
__device__ __forceinline__ float sigf(float x) {
    return fast_rcp(1.0f + fast_ex2(-1.4426950408889634f * x));
}
__device__ __forceinline__ float tanhfast(float x) {
    return 2.0f * fast_rcp(1.0f + fast_ex2(-2.8853900817779268f * x)) - 1.0f;
}

__device__ __forceinline__ float4 gload4(const float* p, int k0, int K) {
    if (k0 + 3 < K) return *(const float4*)p;
    float4 v = make_float4(0.f, 0.f, 0.f, 0.f);
    if (k0 < K)     v.x = p[0];
    if (k0 + 1 < K) v.y = p[1];
    if (k0 + 2 < K) v.z = p[2];
    return v;
}

// ============================================================================
// W1x fragment prep (rows 0..511 of W1) — unchanged.
// ============================================================================
__global__ __launch_bounds__(256) void wprep1(
    const float* __restrict__ WL1, const float* __restrict__ WR1)
{
    const int e = blockIdx.y, s = blockIdx.x, u0 = s * 16;
    const float* Wx = e ? WR1 : WL1;
    uint2* dst = g_W1f[e][s];
    const int tid = threadIdx.x;
#pragma unroll 4
    for (int i = 0; i < 32; i++) {
        int idx = tid + 256 * i;
        int ln = idx & 31, nt = (idx >> 5) & 7, kg = idx >> 8;
        int n = nt * 8 + (ln >> 2);
        int k0 = kg * 16 + (ln & 3) * 2;
        int col = ((n >> 4) << 9) + u0 + (n & 15);
        dst[idx] = make_uint2(
            h2bits(Wx[(size_t)k0 * G4 + col], Wx[(size_t)(k0 + 1) * G4 + col]),
            h2bits(Wx[(size_t)(k0 + 8) * G4 + col], Wx[(size_t)(k0 + 9) * G4 + col]));
    }
}

// ============================================================================
// Layer-0 input projection via fp16 mma.sync (embed, K=300) — unchanged.
// ============================================================================
#define XA_PITCH 48

__global__ __launch_bounds__(256) void xproj_mma(
    const float* __restrict__ AL, const float* __restrict__ AR,
    const float* __restrict__ WL, const float* __restrict__ WR,
    const float* __restrict__ bL, const float* __restrict__ bR,
    int K)
{
    __shared__ __align__(16) char Asm[128 * XA_PITCH];
    __shared__ __align__(16) char Wsm[128 * XA_PITCH];

    const int e = blockIdx.z;
    const float* A    = e ? AR : AL;
    const float* W    = e ? WR : WL;
    const float* bias = e ? bR : bL;
    float* Out = g_X[e];

    const int m0 = blockIdx.x * 128;
    const int n0 = blockIdx.y * 128;
    const int tid = threadIdx.x, lane = tid & 31, wid = tid >> 5;
    const int wm = wid & 1, wn = wid >> 1;
    const int gid = lane >> 2, tig = lane & 3;
    const int tt = m0 >> 8;

    float d[4][4][4];
#pragma unroll
    for (int a = 0; a < 4; a++)
#pragma unroll
        for (int b = 0; b < 4; b++)
#pragma unroll
            for (int c = 0; c < 4; c++) d[a][b][c] = 0.0f;

    const int arow = tid >> 1, ag = tid & 1;
    const int wg = tid >> 7, wtk = (tid >> 5) & 3, wcc = tid & 31;
    const size_t arow_off = ((size_t)((m0 & 255) + arow) * Tn + tt) * K;

    const int nk = (K + 15) >> 4;
    for (int kc16 = 0; kc16 < nk; kc16++) {
        const int kc = kc16 * 16;
        __syncthreads();
        {
            const float* ap = A + arow_off + kc + ag * 8;
            int kb = kc + ag * 8;
            float4 lo = (kb     < K) ? gload4(ap, kb, K)
                                     : make_float4(0.f, 0.f, 0.f, 0.f);
            float4 hi = (kb + 4 < K) ? gload4(ap + 4, kb + 4, K)
                                     : make_float4(0.f, 0.f, 0.f, 0.f);
            char* dst = Asm + arow * XA_PITCH + ag * 4;
            *(uint32_t*)(dst + 0)  = h2bits(lo.x, lo.y);
            *(uint32_t*)(dst + 8)  = h2bits(lo.z, lo.w);
            *(uint32_t*)(dst + 16) = h2bits(hi.x, hi.y);
            *(uint32_t*)(dst + 24) = h2bits(hi.z, hi.w);
        }
        {
            int k1 = kc + wg * 8 + wtk * 2;
            const float* wp1 = W + (size_t)k1 * G4 + n0 + wcc * 4;
            const float* wp2 = W + (size_t)(k1 + 1) * G4 + n0 + wcc * 4;
            float4 lo = (k1     < K) ? *(const float4*)wp1
                                     : make_float4(0.f, 0.f, 0.f, 0.f);
            float4 hi = (k1 + 1 < K) ? *(const float4*)wp2
                                     : make_float4(0.f, 0.f, 0.f, 0.f);
            int off = wtk * 8 + wg * 4;
            *(uint32_t*)(Wsm + (wcc * 4 + 0) * XA_PITCH + off) = h2bits(lo.x, hi.x);
            *(uint32_t*)(Wsm + (wcc * 4 + 1) * XA_PITCH + off) = h2bits(lo.y, hi.y);
            *(uint32_t*)(Wsm + (wcc * 4 + 2) * XA_PITCH + off) = h2bits(lo.z, hi.z);
            *(uint32_t*)(Wsm + (wcc * 4 + 3) * XA_PITCH + off) = h2bits(lo.w, hi.w);
        }
        __syncthreads();
        {
            uint2 bf[4];
#pragma unroll
            for (int j = 0; j < 4; j++) {
                int col = wn * 32 + j * 8 + gid;
                bf[j] = *(const uint2*)(Wsm + col * XA_PITCH + tig * 8);
            }
#pragma unroll
            for (int ms = 0; ms < 4; ms++) {
                int R = wm * 64 + ms * 16;
                uint2 alo = *(const uint2*)(Asm + (R + gid) * XA_PITCH + tig * 8);
                uint2 ahi = *(const uint2*)(Asm + (R + 8 + gid) * XA_PITCH + tig * 8);
#pragma unroll
                for (int j = 0; j < 4; j++)
                    mma16(d[ms][j], alo.x, ahi.x, alo.y, ahi.y, bf[j].x, bf[j].y);
            }
        }
    }

#pragma unroll
    for (int ms = 0; ms < 4; ms++) {
        int r = m0 + wm * 64 + ms * 16 + gid;
#pragma unroll
        for (int j = 0; j < 4; j++) {
            int n = n0 + wn * 32 + j * 8 + tig * 2;
            float2 bv = *(const float2*)&bias[n];
            *(float2*)&Out[(size_t)r * G4 + n] =
                make_float2(d[ms][j][0] + bv.x, d[ms][j][1] + bv.y);
            *(float2*)&Out[(size_t)(r + 8) * G4 + n] =
                make_float2(d[ms][j][2] + bv.x, d[ms][j][3] + bv.y);
        }
    }
}

// ============================================================================
// Fused two-layer persistent LSTM. 128 CTAs = e(2) x m(2) x s(32), 512 thr.
// Per tau: ONE combined pipeline on h0[tau-1] with GEMM-split warps
// (wk=0: W0h resident -> z0; wk=1: W1x streamed -> z1x, kept in registers),
// epilogue-0, then B2 pipeline h1[tau-2]@W1h (k-split, wk1 continues on z1x),
// epilogue-1. One group barrier per tau.
// ============================================================================
#define WB0_OFF   0
#define WB1_OFF   65536
#define STG_OFF   131072
#define H_STG     32768
#define B1_STG    49152
#define ZS_FLTS   (128 * 66)
#define SMEM_DYN  (STG_OFF + 3 * H_STG)        // 229376

__global__ __launch_bounds__(512, 1) void lstm_fused(
    const float* __restrict__ W0L, const float* __restrict__ W0R,
    const float* __restrict__ W1L, const float* __restrict__ W1R,
    const float* __restrict__ b1L, const float* __restrict__ b1R)
{
    extern __shared__ __align__(16) char sm[];
    uint2* WB0 = (uint2*)(sm + WB0_OFF);
    uint2* WB1 = (uint2*)(sm + WB1_OFF);
    float* zs0 = (float*)(sm + STG_OFF);
    float* zs1 = zs0 + ZS_FLTS;
    const uint32_t smb = smem_u32(sm);
    const uint32_t stgb = smb + STG_OFF;

    const int tid = threadIdx.x, lane = tid & 31, wid = tid >> 5;
    const int wk = wid >> 3;
    const int wm = (wid >> 1) & 3, wn = wid & 1;
    const int gid = lane >> 2, tig = lane & 3;
    const int e = blockIdx.x >> 6;
    const int m = (blockIdx.x >> 5) & 1;
    const int s = blockIdx.x & 31;
    const int grp = blockIdx.x >> 5;
    const int m0 = m * 128, u0 = s * 16;

    const float* W0h = (e ? W0R : W0L) + (size_t)Dn * G4;
    const float* W1h = (e ? W1R : W1L) + (size_t)Hn * G4;
    const float* B1  = e ? b1R : b1L;
    const float* X   = g_X[e];

    // ---- resident W fragments (W0h, W1h) ----
#pragma unroll 2
    for (int i = 0; i < 16; i++) {
        int idx = tid + 512 * i;
        int ln = idx & 31, nt = (idx >> 5) & 7, kg = idx >> 8;
        int n = nt * 8 + (ln >> 2);
        int k0 = kg * 16 + (ln & 3) * 2;
        int col = ((n >> 4) << 9) + u0 + (n & 15);
        WB0[idx] = make_uint2(
            h2bits(W0h[(size_t)k0 * G4 + col], W0h[(size_t)(k0 + 1) * G4 + col]),
            h2bits(W0h[(size_t)(k0 + 8) * G4 + col], W0h[(size_t)(k0 + 9) * G4 + col]));
        WB1[idx] = make_uint2(
            h2bits(W1h[(size_t)k0 * G4 + col], W1h[(size_t)(k0 + 1) * G4 + col]),
            h2bits(W1h[(size_t)(k0 + 8) * G4 + col], W1h[(size_t)(k0 + 9) * G4 + col]));
    }

    float creg0[4], creg1[4], b1v[4];
#pragma unroll
    for (int i = 0; i < 4; i++) { creg0[i] = 0.0f; creg1[i] = 0.0f; }
    const int eu = tid & 15, erg = (tid >> 4) & 31;
#pragma unroll
    for (int g = 0; g < 4; g++) b1v[g] = B1[(g << 9) + u0 + eu];

    const int crow = tid >> 2, cb = (tid & 3) * 2;
    const int p_img = s * 16 + ((eu & 7) >> 1) * 4 + ((eu >> 3) & 1) * 2 + (eu & 1);

    float xg[4][4];
    {
        const float* Xt = X + (size_t)m0 * G4 + u0;
#pragma unroll
        for (int q = 0; q < 4; q++) {
            const float* Xb = Xt + (size_t)(erg + 32 * q) * G4;
            xg[0][q] = Xb[eu];   xg[1][q] = Xb[512 + eu];
            xg[2][q] = Xb[1024 + eu]; xg[3][q] = Xb[1536 + eu];
        }
    }

    __syncthreads();

#define ISSUE_H(hg_, kc_, dstb_) do {                                       \
    u64 srcb = (hg_) + (u64)crow * 1024 + (u64)(kc_) * 256;                 \
    uint32_t da0 = (dstb_) + crow * 256 + (((cb)     ^ (crow & 7)) << 5);   \
    uint32_t da1 = (dstb_) + crow * 256 + (((cb + 1) ^ (crow & 7)) << 5);   \
    asm volatile("cp.async.cg.shared.global [%0], [%1], 16;" :: "r"(da0), "l"(srcb + cb * 32)); \
    asm volatile("cp.async.cg.shared.global [%0], [%1], 16;" :: "r"(da0 + 16), "l"(srcb + cb * 32 + 16)); \
    asm volatile("cp.async.cg.shared.global [%0], [%1], 16;" :: "r"(da1), "l"(srcb + cb * 32 + 32)); \
    asm volatile("cp.async.cg.shared.global [%0], [%1], 16;" :: "r"(da1 + 16), "l"(srcb + cb * 32 + 48)); \
} while (0)
#define ISSUE_W(wg_, kc_, dstb_) do {                                       \
    u64 srcw = (wg_) + (u64)(kc_) * 16384 + (u64)tid * 32;                  \
    uint32_t dw = (dstb_) + tid * 32;                                       \
    asm volatile("cp.async.cg.shared.global [%0], [%1], 16;" :: "r"(dw), "l"(srcw)); \
    asm volatile("cp.async.cg.shared.global [%0], [%1], 16;" :: "r"(dw + 16), "l"(srcw + 16)); \
} while (0)
#define COMMIT() asm volatile("cp.async.commit_group;")
#define WAITG(n_) asm volatile("cp.async.wait_group %0;" :: "n"(n_) : "memory")

    for (int tau = 0; tau <= Tn; tau++) {
        float d[2][4][4];
#pragma unroll
        for (int a = 0; a < 2; a++)
#pragma unroll
            for (int b = 0; b < 4; b++)
#pragma unroll
                for (int c = 0; c < 4; c++) d[a][b][c] = 0.0f;

        // ===== combined pipeline: h0[tau-1] vs {W0h (wk0), W1x (wk1)} =====
        if (tau >= 1) {
            const u64 hg = gaddr(&g_Hph[0][e][tau - 1][m][0]);
            const u64 wg = gaddr(&g_W1f[e][s][0]);
            ISSUE_H(hg, 0, stgb); ISSUE_W(wg, 0, stgb + H_STG); COMMIT();
            ISSUE_H(hg, 1, stgb + B1_STG); ISSUE_W(wg, 1, stgb + B1_STG + H_STG); COMMIT();
            for (int kc = 0; kc < 4; kc++) {
                if (kc < 3) WAITG(1); else WAITG(0);
                __syncthreads();
                const char* stg = sm + STG_OFF + (kc & 1) * B1_STG;
                const uint2* wsrc = wk ? (const uint2*)(stg + H_STG)
                                       : (WB0 + kc * 2048);
#pragma unroll
                for (int gl = 0; gl < 8; gl++) {
                    uint2 bf[4];
                    const uint2* wbp = wsrc + (gl * 8 + wn * 4) * 32 + lane;
#pragma unroll
                    for (int j = 0; j < 4; j++) bf[j] = wbp[j * 32];
#pragma unroll
                    for (int ms = 0; ms < 2; ms++) {
                        int rlo = wm * 32 + ms * 16 + gid, rhi = rlo + 8;
                        uint2 alo = *(const uint2*)(stg + rlo * 256 +
                                        ((gl ^ (rlo & 7)) << 5) + tig * 8);
                        uint2 ahi = *(const uint2*)(stg + rhi * 256 +
                                        ((gl ^ (rhi & 7)) << 5) + tig * 8);
#pragma unroll
                        for (int j = 0; j < 4; j++)
                            mma16(d[ms][j], alo.x, ahi.x, alo.y, ahi.y,
                                  bf[j].x, bf[j].y);
                    }
                }
                if (kc + 2 < 4) {
                    __syncthreads();
                    ISSUE_H(hg, kc + 2, stgb + (kc & 1) * B1_STG);
                    ISSUE_W(wg, kc + 2, stgb + (kc & 1) * B1_STG + H_STG);
                    COMMIT();
                }
            }
            __syncthreads();
        }

        // ===== epilogue-0 (L0 step tau) =====
        if (tau < Tn) {
            if (tau >= 1) {
                if (wk == 0) {   // dump z0 fragments
#pragma unroll
                    for (int ms = 0; ms < 2; ms++) {
                        int r0 = wm * 32 + ms * 16 + gid;
#pragma unroll
                        for (int j = 0; j < 4; j++) {
                            int c = wn * 32 + j * 8 + tig * 2;
                            *(float2*)&zs0[r0 * 66 + c] =
                                make_float2(d[ms][j][0], d[ms][j][1]);
                            *(float2*)&zs0[(r0 + 8) * 66 + c] =
                                make_float2(d[ms][j][2], d[ms][j][3]);
                        }
                    }
                }
                __syncthreads();
            }
            {
                __half* hw = &g_Hph[0][e][tau][m][0];
#pragma unroll
                for (int q = 0; q < 4; q++) {
                    int row = erg + 32 * q;
                    float zi = xg[0][q], zj = xg[1][q];
                    float zf = xg[2][q], zo = xg[3][q];
                    if (tau > 0) {
                        zi += zs0[row * 66 + eu];
                        zj += zs0[row * 66 + 16 + eu];
                        zf += zs0[row * 66 + 32 + eu];
                        zo += zs0[row * 66 + 48 + eu];
                    }
                    float cn = creg0[q] * sigf(zf + 1.0f) + sigf(zi) * tanhfast(zj);
                    creg0[q] = cn;
                    hw[row * 512 + p_img] = __float2half_rn(tanhfast(cn) * sigf(zo));
                }
            }
            __syncthreads();   // zs0 reads done before B2 staging
        }

        // wk0 restarts accumulation (z0 consumed); wk1 keeps z1x
        if (wk == 0) {
#pragma unroll
            for (int a = 0; a < 2; a++)
#pragma unroll
                for (int b = 0; b < 4; b++)
#pragma unroll
                    for (int c = 0; c < 4; c++) d[a][b][c] = 0.0f;
        }

        // ===== B2: h1[tau-2] @ W1h (resident), k-split =====
        if (tau >= 2) {
            const u64 hg = gaddr(&g_Hph[1][e][tau - 2][m][0]);
            ISSUE_H(hg, 0, stgb); COMMIT();
            ISSUE_H(hg, 1, stgb + H_STG); COMMIT();
            for (int kc = 0; kc < 4; kc++) {
                if (kc < 3) WAITG(1); else WAITG(0);
                __syncthreads();
                if (kc + 2 < 4) {
                    ISSUE_H(hg, kc + 2, stgb + ((kc + 2) % 3) * H_STG);
                    COMMIT();
                }
                const char* stg = sm + STG_OFF + (kc % 3) * H_STG;
                const uint2* wc = WB1 + kc * 2048;
#pragma unroll
                for (int j8 = 0; j8 < 4; j8++) {
                    int gl = wk * 4 + j8;
                    uint2 bf[4];
                    const uint2* wbp = wc + (gl * 8 + wn * 4) * 32 + lane;
#pragma unroll
                    for (int j = 0; j < 4; j++) bf[j] = wbp[j * 32];
#pragma unroll
                    for (int ms = 0; ms < 2; ms++) {
                        int rlo = wm * 32 + ms * 16 + gid, rhi = rlo + 8;
                        uint2 alo = *(const uint2*)(stg + rlo * 256 +
                                        ((gl ^ (rlo & 7)) << 5) + tig * 8);
                        uint2 ahi = *(const uint2*)(stg + rhi * 256 +
                                        ((gl ^ (rhi & 7)) << 5) + tig * 8);
#pragma unroll
                        for (int j = 0; j < 4; j++)
                            mma16(d[ms][j], alo.x, ahi.x, alo.y, ahi.y,
                                  bf[j].x, bf[j].y);
                    }
                }
            }
        }

        // ===== epilogue-1 (L1 step tau-1) =====
        if (tau >= 1) {
            __syncthreads();
            float* zsw = wk ? zs1 : zs0;
#pragma unroll
            for (int ms = 0; ms < 2; ms++) {
                int r0 = wm * 32 + ms * 16 + gid;
#pragma unroll
                for (int j = 0; j < 4; j++) {
                    int c = wn * 32 + j * 8 + tig * 2;
                    *(float2*)&zsw[r0 * 66 + c] =
                        make_float2(d[ms][j][0], d[ms][j][1]);
                    *(float2*)&zsw[(r0 + 8) * 66 + c] =
                        make_float2(d[ms][j][2], d[ms][j][3]);
                }
            }
            __syncthreads();
            {
                __half* hw = &g_Hph[1][e][tau - 1][m][0];
                float* hr = g_H1[e] + ((size_t)(tau - 1) * Bn + m0) * Hn + u0;
#pragma unroll
                for (int q = 0; q < 4; q++) {
                    int row = erg + 32 * q;
                    float zi = b1v[0] + zs0[row * 66 + eu]      + zs1[row * 66 + eu];
                    float zj = b1v[1] + zs0[row * 66 + 16 + eu] + zs1[row * 66 + 16 + eu];
                    float zf = b1v[2] + zs0[row * 66 + 32 + eu] + zs1[row * 66 + 32 + eu];
                    float zo = b1v[3] + zs0[row * 66 + 48 + eu] + zs1[row * 66 + 48 + eu];
                    float cn = creg1[q] * sigf(zf + 1.0f) + sigf(zi) * tanhfast(zj);
                    creg1[q] = cn;
                    float hv = tanhfast(cn) * sigf(zo);
                    hr[(size_t)row * Hn + eu] = hv;
                    hw[row * 512 + p_img] = __float2half_rn(hv);
                }
            }
        }

        // ===== X prefetch + group barrier =====
        if (tau < Tn) {
            if (tau < Tn - 1) {
                const float* Xt = X + ((size_t)(tau + 1) * Bn + m0) * G4 + u0;
#pragma unroll
                for (int q = 0; q < 4; q++) {
                    const float* Xb = Xt + (size_t)(erg + 32 * q) * G4;
                    xg[0][q] = Xb[eu];   xg[1][q] = Xb[512 + eu];
                    xg[2][q] = Xb[1024 + eu]; xg[3][q] = Xb[1536 + eu];
                }
            }
            __threadfence();
            __syncthreads();
            if (tid == 0) {
                int g = *((volatile int*)&g_gen4[grp]);
                if (atomicAdd(&g_cnt4[grp], 1) == 31) {
                    g_cnt4[grp] = 0;
                    __threadfence();
                    atomicAdd(&g_gen4[grp], 1);
                } else {
                    while (*((volatile int*)&g_gen4[grp]) == g) { }
                }
            }
            __syncthreads();
        }
    }
#undef ISSUE_H
#undef ISSUE_W
#undef COMMIT
#undef WAITG
}

// ============================================================================
// Gather + final projection: 32 CTAs x 8 batch rows (amortizes trans_W reads).
// ============================================================================
__global__ __launch_bounds__(256) void final_kernel(
    const int* __restrict__ lenL, const int* __restrict__ lenR,
    const float* __restrict__ Wt, float* __restrict__ out)
{
    __shared__ float v[8][1032];
    const int tid = threadIdx.x;
    const int b0 = blockIdx.x * 8;
#pragma unroll
    for (int r = 0; r < 8; r++) {
        int b = b0 + r;
        int iL = lenL[b] - 1, iR = lenR[b] - 1;
        const float* hL = &g_H1[0][((size_t)iL * Bn + b) * Hn];
        const float* hR = &g_H1[1][((size_t)iR * Bn + b) * Hn];
        for (int k = tid; k < Hn; k += 256) {
            v[r][k] = hL[k];
            v[r][Hn + k] = hR[k];
        }
    }
    __syncthreads();
    if (tid < OUTD) {
        float acc[8];
#pragma unroll
        for (int r = 0; r < 8; r++) acc[r] = 0.0f;
#pragma unroll 4
        for (int k = 0; k < 2 * Hn; k++) {
            float w = Wt[k * OUTD + tid];
#pragma unroll
            for (int r = 0; r < 8; r++) acc[r] += v[r][k] * w;
        }
#pragma unroll
        for (int r = 0; r < 8; r++)
            out[(b0 + r) * OUTD + tid] = acc[r];
    }
}

// ============================================================================
extern "C" void kernel_launch(void* const* d_in, const int* in_sizes, int n_in,
                              void* d_out, int out_size)
{
    const float* left  = (const float*)d_in[0];
    const float* right = (const float*)d_in[1];
    const int*   lenL  = (const int*)d_in[2];
    const int*   lenR  = (const int*)d_in[3];
    const float* lW0 = (const float*)d_in[4];
    const float* lb0 = (const float*)d_in[5];
    const float* lW1 = (const float*)d_in[6];
    const float* lb1 = (const float*)d_in[7];
    const float* rW0 = (const float*)d_in[8];
    const float* rb0 = (const float*)d_in[9];
    const float* rW1 = (const float*)d_in[10];
    const float* rb1 = (const float*)d_in[11];
    const float* tW  = (const float*)d_in[12];
    float* out = (float*)d_out;

    static int smem_set = 0;
    if (!smem_set) {
        cudaFuncSetAttribute(lstm_fused,
                             cudaFuncAttributeMaxDynamicSharedMemorySize, SMEM_DYN);
        smem_set = 1;
    }

    dim3 gx(256, 16, 2);
    dim3 gw(32, 2);

    wprep1<<<gw, 256>>>(lW1, rW1);
    xproj_mma<<<gx, 256>>>(left, right, lW0, rW0, lb0, rb0, Dn);
    lstm_fused<<<128, 512, SMEM_DYN>>>(lW0, rW0, lW1, rW1, lb1, rb1);
    final_kernel<<<32, 256>>>(lenL, lenR, tW, out);
}